// round 1
// baseline (speedup 1.0000x reference)
#include <cuda_runtime.h>
#include <cuda_bf16.h>
#include <math_constants.h>

// Problem constants (from reference setup_inputs)
#define BB 8
#define TT 8192
#define DD 512
#define QQ 1024
#define CC 4096
#define MM (BB * TT)   // 65536 rows

// Scratch (allocation-free rule: __device__ globals)
__device__ float g_xnorm[(size_t)MM * DD];     // 134 MB
__device__ float g_targets[(size_t)MM * QQ];   // 268 MB
__device__ float g_csq[CC];

// ---------------------------------------------------------------------------
// LayerNorm over D=512. One block (256 threads) per row.
// ---------------------------------------------------------------------------
__global__ __launch_bounds__(256) void ln_kernel(const float* __restrict__ x,
                                                 const float* __restrict__ gamma,
                                                 const float* __restrict__ beta) {
    int r = blockIdx.x;
    const float* xr = x + (size_t)r * DD;
    float* orow = g_xnorm + (size_t)r * DD;
    int t = threadIdx.x;

    float v0 = xr[t];
    float v1 = xr[t + 256];
    float s  = v0 + v1;
    float ss = v0 * v0 + v1 * v1;

    #pragma unroll
    for (int off = 16; off > 0; off >>= 1) {
        s  += __shfl_down_sync(0xFFFFFFFFu, s,  off);
        ss += __shfl_down_sync(0xFFFFFFFFu, ss, off);
    }

    __shared__ float sh_s[8], sh_ss[8];
    int w = t >> 5, l = t & 31;
    if (l == 0) { sh_s[w] = s; sh_ss[w] = ss; }
    __syncthreads();
    if (t == 0) {
        float S = 0.f, SS = 0.f;
        #pragma unroll
        for (int i = 0; i < 8; i++) { S += sh_s[i]; SS += sh_ss[i]; }
        sh_s[0]  = S * (1.0f / DD);
        sh_ss[0] = SS * (1.0f / DD);
    }
    __syncthreads();
    float mu  = sh_s[0];
    float var = sh_ss[0] - mu * mu;
    float rs  = rsqrtf(var + 1e-5f);

    orow[t]       = (v0 - mu) * rs * gamma[t]       + beta[t];
    orow[t + 256] = (v1 - mu) * rs * gamma[t + 256] + beta[t + 256];
}

// ---------------------------------------------------------------------------
// c_sq[c] = sum_q code_book[q, c]^2   (code_book is (Q, C) row-major)
// ---------------------------------------------------------------------------
__global__ __launch_bounds__(256) void csq_kernel(const float* __restrict__ cb) {
    int c = blockIdx.x * blockDim.x + threadIdx.x;  // 0..4095
    float s = 0.f;
    #pragma unroll 4
    for (int q = 0; q < QQ; q++) {
        float v = cb[(size_t)q * CC + c];
        s += v * v;
    }
    g_csq[c] = s;
}

// ---------------------------------------------------------------------------
// SGEMM (TN): C[M,N] = A[M,K] * W[N,K]^T (+ bias). 128x128x8 tiles,
// 256 threads, 8x8 microtile per thread. grid = (N/128, M/128)
// ---------------------------------------------------------------------------
__global__ __launch_bounds__(256) void sgemm_tn(const float* __restrict__ A,
                                                const float* __restrict__ W,
                                                const float* __restrict__ bias,
                                                float* __restrict__ Cout,
                                                int M, int N, int K) {
    __shared__ __align__(16) float As[8][128];
    __shared__ __align__(16) float Bs[8][128];

    int tid = threadIdx.x;
    int bm = blockIdx.y * 128;
    int bn = blockIdx.x * 128;

    int lrow = tid >> 1;          // 0..127
    int lq   = (tid & 1) * 4;     // 0 or 4

    const float* Aptr = A + (size_t)(bm + lrow) * K + lq;
    const float* Wptr = W + (size_t)(bn + lrow) * K + lq;

    int ty = tid >> 4;            // 0..15
    int tx = tid & 15;            // 0..15

    float acc[8][8];
    #pragma unroll
    for (int i = 0; i < 8; i++)
        #pragma unroll
        for (int j = 0; j < 8; j++) acc[i][j] = 0.f;

    for (int kk = 0; kk < K; kk += 8) {
        float4 a4 = *(const float4*)(Aptr + kk);
        float4 b4 = *(const float4*)(Wptr + kk);
        As[lq + 0][lrow] = a4.x; As[lq + 1][lrow] = a4.y;
        As[lq + 2][lrow] = a4.z; As[lq + 3][lrow] = a4.w;
        Bs[lq + 0][lrow] = b4.x; Bs[lq + 1][lrow] = b4.y;
        Bs[lq + 2][lrow] = b4.z; Bs[lq + 3][lrow] = b4.w;
        __syncthreads();

        #pragma unroll
        for (int k = 0; k < 8; k++) {
            float ar[8], br[8];
            float4 a0 = *(const float4*)&As[k][ty * 8];
            float4 a1 = *(const float4*)&As[k][ty * 8 + 4];
            float4 b0 = *(const float4*)&Bs[k][tx * 8];
            float4 b1 = *(const float4*)&Bs[k][tx * 8 + 4];
            ar[0]=a0.x; ar[1]=a0.y; ar[2]=a0.z; ar[3]=a0.w;
            ar[4]=a1.x; ar[5]=a1.y; ar[6]=a1.z; ar[7]=a1.w;
            br[0]=b0.x; br[1]=b0.y; br[2]=b0.z; br[3]=b0.w;
            br[4]=b1.x; br[5]=b1.y; br[6]=b1.z; br[7]=b1.w;
            #pragma unroll
            for (int i = 0; i < 8; i++)
                #pragma unroll
                for (int j = 0; j < 8; j++)
                    acc[i][j] = fmaf(ar[i], br[j], acc[i][j]);
        }
        __syncthreads();
    }

    float bv[8];
    #pragma unroll
    for (int j = 0; j < 8; j++)
        bv[j] = bias ? bias[bn + tx * 8 + j] : 0.f;

    #pragma unroll
    for (int i = 0; i < 8; i++) {
        float* crow = Cout + (size_t)(bm + ty * 8 + i) * N + bn + tx * 8;
        #pragma unroll
        for (int j = 0; j < 8; j++) crow[j] = acc[i][j] + bv[j];
    }
}

// ---------------------------------------------------------------------------
// Fused cross-GEMM + argmin:
//   labels[m] = argmin_c ( c_sq[c] - 2 * sum_q targets[m,q]*code_book[q,c] )
// (sqrt, max(.,0) and per-row t_sq are monotone/constant -> same argmin)
// Block: 128 rows; loops over C in 128-wide chunks. grid = M/128.
// ---------------------------------------------------------------------------
__global__ __launch_bounds__(256) void cross_argmin_kernel(const float* __restrict__ cb,
                                                           float* __restrict__ labels_out) {
    __shared__ __align__(16) float As[8][128];
    __shared__ __align__(16) float Bs[8][128];
    __shared__ float s_v[128][16];
    __shared__ int   s_i[128][16];

    int tid = threadIdx.x;
    int bm = blockIdx.x * 128;

    int lrowA = tid >> 1;         // 0..127
    int lqA   = (tid & 1) * 4;    // 0 or 4
    int lrowB = tid >> 5;         // 0..7
    int lcB   = (tid & 31) * 4;   // 0..124

    int ty = tid >> 4;
    int tx = tid & 15;

    const float* Abase = g_targets + (size_t)(bm + lrowA) * QQ + lqA;

    float minv[8];
    int   mini[8];
    #pragma unroll
    for (int i = 0; i < 8; i++) { minv[i] = CUDART_INF_F; mini[i] = 0; }

    for (int c0 = 0; c0 < CC; c0 += 128) {
        float acc[8][8];
        #pragma unroll
        for (int i = 0; i < 8; i++)
            #pragma unroll
            for (int j = 0; j < 8; j++) acc[i][j] = 0.f;

        for (int kk = 0; kk < QQ; kk += 8) {
            float4 a4 = *(const float4*)(Abase + kk);
            As[lqA + 0][lrowA] = a4.x; As[lqA + 1][lrowA] = a4.y;
            As[lqA + 2][lrowA] = a4.z; As[lqA + 3][lrowA] = a4.w;

            float4 b4 = *(const float4*)(cb + (size_t)(kk + lrowB) * CC + c0 + lcB);
            *(float4*)&Bs[lrowB][lcB] = b4;
            __syncthreads();

            #pragma unroll
            for (int k = 0; k < 8; k++) {
                float ar[8], br[8];
                float4 a0 = *(const float4*)&As[k][ty * 8];
                float4 a1 = *(const float4*)&As[k][ty * 8 + 4];
                float4 b0 = *(const float4*)&Bs[k][tx * 8];
                float4 b1 = *(const float4*)&Bs[k][tx * 8 + 4];
                ar[0]=a0.x; ar[1]=a0.y; ar[2]=a0.z; ar[3]=a0.w;
                ar[4]=a1.x; ar[5]=a1.y; ar[6]=a1.z; ar[7]=a1.w;
                br[0]=b0.x; br[1]=b0.y; br[2]=b0.z; br[3]=b0.w;
                br[4]=b1.x; br[5]=b1.y; br[6]=b1.z; br[7]=b1.w;
                #pragma unroll
                for (int i = 0; i < 8; i++)
                    #pragma unroll
                    for (int j = 0; j < 8; j++)
                        acc[i][j] = fmaf(ar[i], br[j], acc[i][j]);
            }
            __syncthreads();
        }

        #pragma unroll
        for (int i = 0; i < 8; i++) {
            #pragma unroll
            for (int j = 0; j < 8; j++) {
                int c = c0 + tx * 8 + j;
                float score = g_csq[c] - 2.0f * acc[i][j];
                if (score < minv[i]) { minv[i] = score; mini[i] = c; }
            }
        }
    }

    #pragma unroll
    for (int i = 0; i < 8; i++) {
        s_v[ty * 8 + i][tx] = minv[i];
        s_i[ty * 8 + i][tx] = mini[i];
    }
    __syncthreads();

    if (tid < 128) {
        int row = tid;
        float bv = s_v[row][0];
        int   bi = s_i[row][0];
        #pragma unroll
        for (int t = 1; t < 16; t++) {
            float v  = s_v[row][t];
            int   id = s_i[row][t];
            if (v < bv || (v == bv && id < bi)) { bv = v; bi = id; }
        }
        labels_out[bm + row] = (float)bi;
    }
}

extern "C" void kernel_launch(void* const* d_in, const int* in_sizes, int n_in,
                              void* d_out, int out_size) {
    const float* x     = (const float*)d_in[0];
    const float* gamma = (const float*)d_in[1];
    const float* beta  = (const float*)d_in[2];
    const float* projw = (const float*)d_in[3];
    const float* cb    = (const float*)d_in[4];
    const float* encw  = (const float*)d_in[5];
    const float* encb  = (const float*)d_in[6];

    float* out     = (float*)d_out;
    float* enc_out = out;                               // (M, Q) floats
    float* labels  = out + ((size_t)out_size - MM);     // (M,) as float

    float *xn, *tg;
    cudaGetSymbolAddress((void**)&xn, g_xnorm);
    cudaGetSymbolAddress((void**)&tg, g_targets);

    // 1) LayerNorm
    ln_kernel<<<MM, 256>>>(x, gamma, beta);

    // 2) codeword squared norms
    csq_kernel<<<CC / 256, 256>>>(cb);

    // 3) targets = xnorm @ proj_w^T
    dim3 grid(QQ / 128, MM / 128);
    sgemm_tn<<<grid, 256>>>(xn, projw, nullptr, tg, MM, QQ, DD);

    // 4) encoder_out = xnorm @ enc_w^T + enc_b
    sgemm_tn<<<grid, 256>>>(xn, encw, encb, enc_out, MM, QQ, DD);

    // 5) fused cross-GEMM + argmin -> labels
    cross_argmin_kernel<<<MM / 128, 256>>>(cb, labels);

    (void)in_sizes; (void)n_in;
}

// round 3
// speedup vs baseline: 2.3221x; 2.3221x over previous
#include <cuda_runtime.h>
#include <cuda_fp16.h>
#include <math_constants.h>
#include <cstdint>

// Problem constants
#define BB 8
#define TT 8192
#define DD 512
#define QQ 1024
#define CC 4096
#define MM (BB * TT)   // 65536

typedef __half h16;

// ---------------------------------------------------------------------------
// Scratch (__device__ globals; allocation-free rule)
// ---------------------------------------------------------------------------
__device__ __align__(16) h16 g_x_hi[(size_t)MM * DD];
__device__ __align__(16) h16 g_x_lo[(size_t)MM * DD];
__device__ __align__(16) h16 g_t_hi[(size_t)MM * QQ];
__device__ __align__(16) h16 g_t_lo[(size_t)MM * QQ];
__device__ __align__(16) h16 g_cbt_hi[(size_t)CC * QQ];   // codebook^T [C][Q]
__device__ __align__(16) h16 g_cbt_lo[(size_t)CC * QQ];
__device__ __align__(16) h16 g_pw_hi[(size_t)QQ * DD];
__device__ __align__(16) h16 g_pw_lo[(size_t)QQ * DD];
__device__ __align__(16) h16 g_ew_hi[(size_t)QQ * DD];
__device__ __align__(16) h16 g_ew_lo[(size_t)QQ * DD];
__device__ float g_csq[CC];
__device__ unsigned long long g_key[MM];

// ---------------------------------------------------------------------------
// PTX helpers (sm_80-class: cp.async / ldmatrix / mma.sync)
// ---------------------------------------------------------------------------
__device__ __forceinline__ uint32_t smem_u32(const void* p) {
    uint32_t a;
    asm("{ .reg .u64 t; cvta.to.shared.u64 t, %1; cvt.u32.u64 %0, t; }"
        : "=r"(a) : "l"(p));
    return a;
}
__device__ __forceinline__ void cp16(uint32_t dst, const void* src) {
    asm volatile("cp.async.cg.shared.global [%0], [%1], 16;" :: "r"(dst), "l"(src));
}
#define CP_COMMIT() asm volatile("cp.async.commit_group;")
#define CP_WAIT1()  asm volatile("cp.async.wait_group 1;")
#define CP_WAIT0()  asm volatile("cp.async.wait_group 0;")

__device__ __forceinline__ void ldmx4(uint32_t* r, uint32_t addr) {
    asm volatile("ldmatrix.sync.aligned.m8n8.x4.shared.b16 {%0,%1,%2,%3}, [%4];"
                 : "=r"(r[0]), "=r"(r[1]), "=r"(r[2]), "=r"(r[3]) : "r"(addr));
}
__device__ __forceinline__ void mma16816(float* d, const uint32_t* a,
                                         uint32_t b0, uint32_t b1) {
    asm volatile("mma.sync.aligned.m16n8k16.row.col.f32.f16.f16.f32 "
                 "{%0,%1,%2,%3}, {%4,%5,%6,%7}, {%8,%9}, {%0,%1,%2,%3};"
                 : "+f"(d[0]), "+f"(d[1]), "+f"(d[2]), "+f"(d[3])
                 : "r"(a[0]), "r"(a[1]), "r"(a[2]), "r"(a[3]), "r"(b0), "r"(b1));
}

// float -> order-preserving uint32 (ascending)
__device__ __forceinline__ uint32_t ford(float s) {
    uint32_t b = __float_as_uint(s);
    return (b & 0x80000000u) ? ~b : (b | 0x80000000u);
}

// ---------------------------------------------------------------------------
// Unified split-fp16 HGEMM: C[M,N] = A(M,K) @ B(N,K)^T via 3-pass hi/lo split.
//   mode 0: write C split to (oth, otl) fp16 pairs        [targets]
//   mode 1: write C+bias fp32 to outf                      [encoder_out]
//   mode 2: score = csq[c] - 2*C; atomicMin packed argmin  [labels]
// Tiles: BM=BN=128, BK=64. 256 threads (8 warps, 2x4 warp grid, 64x32/warp).
// 2-stage cp.async double buffer. smem = 2 * 4 * 16KB = 128KB.
// ---------------------------------------------------------------------------
#define STG    65536
#define T_AH   0
#define T_AL   16384
#define T_BH   32768
#define T_BL   49152
#define SMEM_TOTAL (2 * STG)

__global__ __launch_bounds__(256, 1) void hgemm_split(
    const h16* __restrict__ Ah, const h16* __restrict__ Al,
    const h16* __restrict__ Bh, const h16* __restrict__ Bl,
    int K, int Ntot, int mode,
    const float* __restrict__ bias,
    float* __restrict__ outf,
    h16* __restrict__ oth, h16* __restrict__ otl)
{
    extern __shared__ __align__(1024) char smem[];
    const uint32_t sb = smem_u32(smem);
    const int tid  = threadIdx.x;
    const int lane = tid & 31;
    const int wid  = tid >> 5;
    const int wy   = wid >> 2;      // 0..1
    const int wx   = wid & 3;       // 0..3
    const size_t bm = (size_t)blockIdx.y * 128;
    const size_t bn = (size_t)blockIdx.x * 128;

    float acc[4][4][4];
    #pragma unroll
    for (int i = 0; i < 4; i++)
        #pragma unroll
        for (int j = 0; j < 4; j++)
            #pragma unroll
            for (int k = 0; k < 4; k++) acc[i][j][k] = 0.f;

    // loader lane mapping: row = tid>>1 (0..127), half = tid&1 (64B each)
    const int lrow = tid >> 1;
    const int lhalf = tid & 1;
    const uint32_t swr = (uint32_t)((lrow & 7) << 4);
    const uint32_t rbase = (uint32_t)(lrow * 128);

    const char* pAh = (const char*)(Ah + (bm + lrow) * (size_t)K);
    const char* pAl = (const char*)(Al + (bm + lrow) * (size_t)K);
    const char* pBh = (const char*)(Bh + (bn + lrow) * (size_t)K);
    const char* pBl = (const char*)(Bl + (bn + lrow) * (size_t)K);

    const int nch = K >> 6;

    // ---- stage loader (issues 16 cp.async + commit) ----
    auto load_stage = [&](int s, int kc) {
        uint32_t st = sb + (uint32_t)s * STG;
        int kbyte0 = kc << 7;                        // kc*64 elements * 2B
        #pragma unroll
        for (int i = 0; i < 4; i++) {
            uint32_t ko = (uint32_t)(lhalf * 64 + i * 16);
            uint32_t d  = rbase + (ko ^ swr);
            cp16(st + T_AH + d, pAh + kbyte0 + ko);
            cp16(st + T_AL + d, pAl + kbyte0 + ko);
            cp16(st + T_BH + d, pBh + kbyte0 + ko);
            cp16(st + T_BL + d, pBl + kbyte0 + ko);
        }
        CP_COMMIT();
    };

    // ---- compute one BK=64 stage ----
    auto compute_stage = [&](int s) {
        uint32_t aHi = sb + (uint32_t)s * STG + T_AH;
        uint32_t aLo = sb + (uint32_t)s * STG + T_AL;
        uint32_t bHi = sb + (uint32_t)s * STG + T_BH;
        uint32_t bLo = sb + (uint32_t)s * STG + T_BL;
        const int rl   = lane & 15;
        const uint32_t kbh = (uint32_t)((lane >> 4) << 4);

        #pragma unroll
        for (int ks = 0; ks < 4; ks++) {
            uint32_t kb = (uint32_t)(ks * 32) + kbh;
            uint32_t a_h[4][4], a_l[4][4], b_h[2][4], b_l[2][4];
            #pragma unroll
            for (int mf = 0; mf < 4; mf++) {
                int r = wy * 64 + mf * 16 + rl;
                uint32_t off = (uint32_t)(r * 128) + (kb ^ (uint32_t)((r & 7) << 4));
                ldmx4(a_h[mf], aHi + off);
                ldmx4(a_l[mf], aLo + off);
            }
            #pragma unroll
            for (int np = 0; np < 2; np++) {
                int n = wx * 32 + np * 16 + rl;
                uint32_t off = (uint32_t)(n * 128) + (kb ^ (uint32_t)((n & 7) << 4));
                ldmx4(b_h[np], bHi + off);
                ldmx4(b_l[np], bLo + off);
            }
            #pragma unroll
            for (int mf = 0; mf < 4; mf++) {
                #pragma unroll
                for (int nf = 0; nf < 4; nf++) {
                    int p = nf >> 1, q = nf & 1;
                    mma16816(acc[mf][nf], a_h[mf], b_h[p][q], b_h[p][q + 2]);
                    mma16816(acc[mf][nf], a_h[mf], b_l[p][q], b_l[p][q + 2]);
                    mma16816(acc[mf][nf], a_l[mf], b_h[p][q], b_h[p][q + 2]);
                }
            }
        }
    };

    // ---- pipelined main loop ----
    load_stage(0, 0);
    for (int kc = 0; kc < nch; kc++) {
        if (kc + 1 < nch) {
            load_stage((kc + 1) & 1, kc + 1);
            CP_WAIT1();
        } else {
            CP_WAIT0();
        }
        __syncthreads();
        compute_stage(kc & 1);
        __syncthreads();
    }

    // ---- epilogue ----
    const int qrow = lane >> 2;             // 0..7
    const int c2   = 2 * (lane & 3);        // 0,2,4,6

    if (mode == 0) {
        #pragma unroll
        for (int mf = 0; mf < 4; mf++) {
            size_t r0 = bm + (size_t)(wy * 64 + mf * 16 + qrow);
            #pragma unroll
            for (int nf = 0; nf < 4; nf++) {
                size_t col = bn + (size_t)(wx * 32 + nf * 8 + c2);
                #pragma unroll
                for (int sub = 0; sub < 2; sub++) {
                    size_t r = r0 + sub * 8;
                    float v0 = acc[mf][nf][sub * 2 + 0];
                    float v1 = acc[mf][nf][sub * 2 + 1];
                    h16 h0 = __float2half(v0);
                    h16 h1 = __float2half(v1);
                    h16 l0 = __float2half(v0 - __half2float(h0));
                    h16 l1 = __float2half(v1 - __half2float(h1));
                    __half2 hp; hp.x = h0; hp.y = h1;
                    __half2 lp; lp.x = l0; lp.y = l1;
                    *(__half2*)(oth + r * Ntot + col) = hp;
                    *(__half2*)(otl + r * Ntot + col) = lp;
                }
            }
        }
    } else if (mode == 1) {
        #pragma unroll
        for (int mf = 0; mf < 4; mf++) {
            size_t r0 = bm + (size_t)(wy * 64 + mf * 16 + qrow);
            #pragma unroll
            for (int nf = 0; nf < 4; nf++) {
                size_t col = bn + (size_t)(wx * 32 + nf * 8 + c2);
                float b0 = bias[col], b1 = bias[col + 1];
                #pragma unroll
                for (int sub = 0; sub < 2; sub++) {
                    size_t r = r0 + sub * 8;
                    float2 o;
                    o.x = acc[mf][nf][sub * 2 + 0] + b0;
                    o.y = acc[mf][nf][sub * 2 + 1] + b1;
                    *(float2*)(outf + r * Ntot + col) = o;
                }
            }
        }
    } else {
        // mode 2: fused argmin over scores = csq[c] - 2*acc
        #pragma unroll
        for (int mf = 0; mf < 4; mf++) {
            #pragma unroll
            for (int sub = 0; sub < 2; sub++) {
                unsigned long long best = 0xFFFFFFFFFFFFFFFFull;
                #pragma unroll
                for (int nf = 0; nf < 4; nf++) {
                    int col = (int)bn + wx * 32 + nf * 8 + c2;
                    #pragma unroll
                    for (int j = 0; j < 2; j++) {
                        float s = g_csq[col + j] - 2.0f * acc[mf][nf][sub * 2 + j];
                        unsigned long long key =
                            ((unsigned long long)ford(s) << 32) | (uint32_t)(col + j);
                        if (key < best) best = key;
                    }
                }
                // reduce across the 4 lanes sharing this row (lanes 4q..4q+3)
                unsigned long long o;
                o = __shfl_down_sync(0xFFFFFFFFu, best, 2);
                if (o < best) best = o;
                o = __shfl_down_sync(0xFFFFFFFFu, best, 1);
                if (o < best) best = o;
                if ((lane & 3) == 0) {
                    size_t row = bm + (size_t)(wy * 64 + mf * 16 + sub * 8 + qrow);
                    atomicMin(&g_key[row], best);
                }
            }
        }
    }
}

// ---------------------------------------------------------------------------
// LayerNorm over D=512, writes fp16 hi/lo split directly.
// ---------------------------------------------------------------------------
__global__ __launch_bounds__(256) void ln_kernel(const float* __restrict__ x,
                                                 const float* __restrict__ gamma,
                                                 const float* __restrict__ beta) {
    int r = blockIdx.x;
    const float* xr = x + (size_t)r * DD;
    int t = threadIdx.x;

    float v0 = xr[t];
    float v1 = xr[t + 256];
    float s  = v0 + v1;
    float ss = v0 * v0 + v1 * v1;

    #pragma unroll
    for (int off = 16; off > 0; off >>= 1) {
        s  += __shfl_down_sync(0xFFFFFFFFu, s,  off);
        ss += __shfl_down_sync(0xFFFFFFFFu, ss, off);
    }
    __shared__ float sh_s[8], sh_ss[8];
    int w = t >> 5, l = t & 31;
    if (l == 0) { sh_s[w] = s; sh_ss[w] = ss; }
    __syncthreads();
    if (t == 0) {
        float S = 0.f, SS = 0.f;
        #pragma unroll
        for (int i = 0; i < 8; i++) { S += sh_s[i]; SS += sh_ss[i]; }
        sh_s[0]  = S * (1.0f / DD);
        sh_ss[0] = SS * (1.0f / DD);
    }
    __syncthreads();
    float mu  = sh_s[0];
    float var = sh_ss[0] - mu * mu;
    float rs  = rsqrtf(var + 1e-5f);

    float y0 = (v0 - mu) * rs * gamma[t]       + beta[t];
    float y1 = (v1 - mu) * rs * gamma[t + 256] + beta[t + 256];

    size_t base = (size_t)r * DD;
    h16 h0 = __float2half(y0);
    h16 h1 = __float2half(y1);
    g_x_hi[base + t]       = h0;
    g_x_hi[base + t + 256] = h1;
    g_x_lo[base + t]       = __float2half(y0 - __half2float(h0));
    g_x_lo[base + t + 256] = __float2half(y1 - __half2float(h1));
}

// ---------------------------------------------------------------------------
// fp32 -> fp16 hi/lo split (weights)
// ---------------------------------------------------------------------------
__global__ __launch_bounds__(256) void split_kernel(const float* __restrict__ src,
                                                    h16* __restrict__ hi,
                                                    h16* __restrict__ lo, int n) {
    int i = blockIdx.x * 256 + threadIdx.x;
    if (i < n) {
        float v = src[i];
        h16 h = __float2half(v);
        hi[i] = h;
        lo[i] = __float2half(v - __half2float(h));
    }
}

// ---------------------------------------------------------------------------
// Codebook transpose + split: cbT[c][q] = split(cb[q][c]). grid (C/32, Q/32)
// ---------------------------------------------------------------------------
__global__ __launch_bounds__(256) void cbt_kernel(const float* __restrict__ cb) {
    __shared__ float t[32][33];
    int c0 = blockIdx.x * 32, q0 = blockIdx.y * 32;
    int tx = threadIdx.x & 31, ty = threadIdx.x >> 5;  // 32 x 8

    #pragma unroll
    for (int r = ty; r < 32; r += 8)
        t[r][tx] = cb[(size_t)(q0 + r) * CC + c0 + tx];
    __syncthreads();
    #pragma unroll
    for (int r = ty; r < 32; r += 8) {
        float v = t[tx][r];   // = cb[q0+tx][c0+r]
        h16 h = __float2half(v);
        size_t idx = (size_t)(c0 + r) * QQ + q0 + tx;
        g_cbt_hi[idx] = h;
        g_cbt_lo[idx] = __float2half(v - __half2float(h));
    }
}

// ---------------------------------------------------------------------------
// c_sq[c] = sum_q cb[q][c]^2
// ---------------------------------------------------------------------------
__global__ __launch_bounds__(256) void csq_kernel(const float* __restrict__ cb) {
    int c = blockIdx.x * 256 + threadIdx.x;
    float s = 0.f;
    #pragma unroll 4
    for (int q = 0; q < QQ; q++) {
        float v = cb[(size_t)q * CC + c];
        s += v * v;
    }
    g_csq[c] = s;
}

// ---------------------------------------------------------------------------
__global__ __launch_bounds__(256) void init_keys() {
    int i = blockIdx.x * 256 + threadIdx.x;
    g_key[i] = 0xFFFFFFFFFFFFFFFFull;
}
__global__ __launch_bounds__(256) void fin_labels(float* __restrict__ labels) {
    int i = blockIdx.x * 256 + threadIdx.x;
    labels[i] = (float)(uint32_t)(g_key[i] & 0xFFFFFFFFull);
}

// ---------------------------------------------------------------------------
extern "C" void kernel_launch(void* const* d_in, const int* in_sizes, int n_in,
                              void* d_out, int out_size) {
    const float* x     = (const float*)d_in[0];
    const float* gamma = (const float*)d_in[1];
    const float* beta  = (const float*)d_in[2];
    const float* projw = (const float*)d_in[3];
    const float* cb    = (const float*)d_in[4];
    const float* encw  = (const float*)d_in[5];
    const float* encb  = (const float*)d_in[6];

    float* out     = (float*)d_out;
    float* enc_out = out;                               // (M, Q) fp32
    float* labels  = out + ((size_t)out_size - MM);     // (M,) as fp32

    h16 *xh, *xl, *th, *tl, *ch, *cl, *pwh, *pwl, *ewh, *ewl;
    cudaGetSymbolAddress((void**)&xh, g_x_hi);
    cudaGetSymbolAddress((void**)&xl, g_x_lo);
    cudaGetSymbolAddress((void**)&th, g_t_hi);
    cudaGetSymbolAddress((void**)&tl, g_t_lo);
    cudaGetSymbolAddress((void**)&ch, g_cbt_hi);
    cudaGetSymbolAddress((void**)&cl, g_cbt_lo);
    cudaGetSymbolAddress((void**)&pwh, g_pw_hi);
    cudaGetSymbolAddress((void**)&pwl, g_pw_lo);
    cudaGetSymbolAddress((void**)&ewh, g_ew_hi);
    cudaGetSymbolAddress((void**)&ewl, g_ew_lo);

    cudaFuncSetAttribute(hgemm_split, cudaFuncAttributeMaxDynamicSharedMemorySize,
                         SMEM_TOTAL);

    // 1) LayerNorm -> fp16 split
    ln_kernel<<<MM, 256>>>(x, gamma, beta);

    // 2) preprocessing
    split_kernel<<<(QQ * DD + 255) / 256, 256>>>(projw, pwh, pwl, QQ * DD);
    split_kernel<<<(QQ * DD + 255) / 256, 256>>>(encw, ewh, ewl, QQ * DD);
    cbt_kernel<<<dim3(CC / 32, QQ / 32), 256>>>(cb);
    csq_kernel<<<CC / 256, 256>>>(cb);
    init_keys<<<MM / 256, 256>>>();

    // 3) targets = xnorm @ proj_w^T  (split fp16 epilogue)
    dim3 grid12(QQ / 128, MM / 128);
    hgemm_split<<<grid12, 256, SMEM_TOTAL>>>(xh, xl, pwh, pwl, DD, QQ, 0,
                                             nullptr, nullptr, th, tl);

    // 4) encoder_out = xnorm @ enc_w^T + enc_b  (fp32 epilogue)
    hgemm_split<<<grid12, 256, SMEM_TOTAL>>>(xh, xl, ewh, ewl, DD, QQ, 1,
                                             encb, enc_out, nullptr, nullptr);

    // 5) cross-GEMM + fused argmin over C
    dim3 gridx(CC / 128, MM / 128);
    hgemm_split<<<gridx, 256, SMEM_TOTAL>>>(th, tl, ch, cl, QQ, CC, 2,
                                            nullptr, nullptr, nullptr, nullptr);

    // 6) finalize labels
    fin_labels<<<MM / 256, 256>>>(labels);

    (void)in_sizes; (void)n_in;
}

// round 4
// speedup vs baseline: 2.3508x; 1.0124x over previous
#include <cuda_runtime.h>
#include <cuda_fp16.h>
#include <math_constants.h>
#include <cstdint>

// Problem constants
#define BB 8
#define TT 8192
#define DD 512
#define QQ 1024
#define CC 4096
#define MM (BB * TT)   // 65536

typedef __half h16;

// ---------------------------------------------------------------------------
// Scratch (__device__ globals; allocation-free rule)
// ---------------------------------------------------------------------------
__device__ __align__(16) h16 g_x_hi[(size_t)MM * DD];
__device__ __align__(16) h16 g_x_lo[(size_t)MM * DD];
__device__ __align__(16) h16 g_t_hi[(size_t)MM * QQ];
__device__ __align__(16) h16 g_t_lo[(size_t)MM * QQ];
__device__ __align__(16) h16 g_cbt_hi[(size_t)CC * QQ];   // codebook^T [C][Q]
__device__ __align__(16) h16 g_cbt_lo[(size_t)CC * QQ];
__device__ __align__(16) h16 g_pw_hi[(size_t)QQ * DD];
__device__ __align__(16) h16 g_pw_lo[(size_t)QQ * DD];
__device__ __align__(16) h16 g_ew_hi[(size_t)QQ * DD];
__device__ __align__(16) h16 g_ew_lo[(size_t)QQ * DD];
__device__ float g_csq[CC];
__device__ unsigned long long g_key[MM];

// ---------------------------------------------------------------------------
// PTX helpers (sm_80-class: cp.async / ldmatrix / mma.sync)
// ---------------------------------------------------------------------------
__device__ __forceinline__ uint32_t smem_u32(const void* p) {
    uint32_t a;
    asm("{ .reg .u64 t; cvta.to.shared.u64 t, %1; cvt.u32.u64 %0, t; }"
        : "=r"(a) : "l"(p));
    return a;
}
__device__ __forceinline__ void cp16(uint32_t dst, const void* src) {
    asm volatile("cp.async.cg.shared.global [%0], [%1], 16;" :: "r"(dst), "l"(src));
}
#define CP_COMMIT() asm volatile("cp.async.commit_group;")
#define CP_WAIT1()  asm volatile("cp.async.wait_group 1;")
#define CP_WAIT0()  asm volatile("cp.async.wait_group 0;")

__device__ __forceinline__ void ldmx4(uint32_t* r, uint32_t addr) {
    asm volatile("ldmatrix.sync.aligned.m8n8.x4.shared.b16 {%0,%1,%2,%3}, [%4];"
                 : "=r"(r[0]), "=r"(r[1]), "=r"(r[2]), "=r"(r[3]) : "r"(addr));
}
__device__ __forceinline__ void mma16816(float* d, const uint32_t* a,
                                         uint32_t b0, uint32_t b1) {
    asm volatile("mma.sync.aligned.m16n8k16.row.col.f32.f16.f16.f32 "
                 "{%0,%1,%2,%3}, {%4,%5,%6,%7}, {%8,%9}, {%0,%1,%2,%3};"
                 : "+f"(d[0]), "+f"(d[1]), "+f"(d[2]), "+f"(d[3])
                 : "r"(a[0]), "r"(a[1]), "r"(a[2]), "r"(a[3]), "r"(b0), "r"(b1));
}

// float -> order-preserving uint32 (ascending)
__device__ __forceinline__ uint32_t ford(float s) {
    uint32_t b = __float_as_uint(s);
    return (b & 0x80000000u) ? ~b : (b | 0x80000000u);
}

// ---------------------------------------------------------------------------
// Unified split-fp16 HGEMM: C[M,N] = A(M,K) @ B(N,K)^T via 3-pass hi/lo split.
//   mode 0: write C split to (oth, otl) fp16 pairs        [targets]
//   mode 1: write C+bias fp32 to outf                      [encoder_out]
//   mode 2: score = csq[c] - 2*C; atomicMin packed argmin  [labels]
// Tiles: BM=BN=128, BK=64. 256 threads (8 warps, 2x4 warp grid, 64x32/warp).
// 3-stage cp.async pipeline, one __syncthreads per chunk. smem = 192KB.
// ---------------------------------------------------------------------------
#define STG    65536
#define T_AH   0
#define T_AL   16384
#define T_BH   32768
#define T_BL   49152
#define NSTAGE 3
#define SMEM_TOTAL (NSTAGE * STG)

__global__ __launch_bounds__(256, 1) void hgemm_split(
    const h16* __restrict__ Ah, const h16* __restrict__ Al,
    const h16* __restrict__ Bh, const h16* __restrict__ Bl,
    int K, int Ntot, int mode,
    const float* __restrict__ bias,
    float* __restrict__ outf,
    h16* __restrict__ oth, h16* __restrict__ otl)
{
    extern __shared__ __align__(1024) char smem[];
    const uint32_t sb = smem_u32(smem);
    const int tid  = threadIdx.x;
    const int lane = tid & 31;
    const int wid  = tid >> 5;
    const int wy   = wid >> 2;      // 0..1
    const int wx   = wid & 3;       // 0..3
    const size_t bm = (size_t)blockIdx.y * 128;
    const size_t bn = (size_t)blockIdx.x * 128;

    float acc[4][4][4];
    #pragma unroll
    for (int i = 0; i < 4; i++)
        #pragma unroll
        for (int j = 0; j < 4; j++)
            #pragma unroll
            for (int k = 0; k < 4; k++) acc[i][j][k] = 0.f;

    // loader lane mapping: row = tid>>1 (0..127), half = tid&1 (64B each)
    const int lrow  = tid >> 1;
    const int lhalf = tid & 1;
    const uint32_t swr   = (uint32_t)((lrow & 7) << 4);
    const uint32_t rbase = (uint32_t)(lrow * 128);

    const char* pAh = (const char*)(Ah + (bm + lrow) * (size_t)K);
    const char* pAl = (const char*)(Al + (bm + lrow) * (size_t)K);
    const char* pBh = (const char*)(Bh + (bn + lrow) * (size_t)K);
    const char* pBl = (const char*)(Bl + (bn + lrow) * (size_t)K);

    const int nch = K >> 6;

    // ---- stage loader (16 cp.async + commit) ----
    auto load_stage = [&](int s, int kc) {
        uint32_t st = sb + (uint32_t)s * STG;
        int kbyte0 = kc << 7;                        // kc*64 elems * 2B
        #pragma unroll
        for (int i = 0; i < 4; i++) {
            uint32_t ko = (uint32_t)(lhalf * 64 + i * 16);
            uint32_t d  = rbase + (ko ^ swr);
            cp16(st + T_AH + d, pAh + kbyte0 + ko);
            cp16(st + T_AL + d, pAl + kbyte0 + ko);
            cp16(st + T_BH + d, pBh + kbyte0 + ko);
            cp16(st + T_BL + d, pBl + kbyte0 + ko);
        }
        CP_COMMIT();
    };

    // ---- precomputed fragment addresses (k-independent parts) ----
    const int rl  = lane & 15;
    const uint32_t kbh = (uint32_t)((lane >> 4) << 4);
    uint32_t a_base[4], a_swz[4], b_base[2], b_swz[2];
    #pragma unroll
    for (int mf = 0; mf < 4; mf++) {
        int r = wy * 64 + mf * 16 + rl;
        a_base[mf] = (uint32_t)(r * 128);
        a_swz[mf]  = (uint32_t)((r & 7) << 4);
    }
    #pragma unroll
    for (int np = 0; np < 2; np++) {
        int n = wx * 32 + np * 16 + rl;
        b_base[np] = (uint32_t)(n * 128);
        b_swz[np]  = (uint32_t)((n & 7) << 4);
    }

    // ---- compute one BK=64 stage ----
    auto compute_stage = [&](int s) {
        uint32_t base = sb + (uint32_t)s * STG;
        uint32_t aHi = base + T_AH, aLo = base + T_AL;
        uint32_t bHi = base + T_BH, bLo = base + T_BL;

        #pragma unroll
        for (int ks = 0; ks < 4; ks++) {
            uint32_t kb = (uint32_t)(ks * 32) + kbh;
            uint32_t a_h[4][4], a_l[4][4], b_h[2][4], b_l[2][4];
            #pragma unroll
            for (int mf = 0; mf < 4; mf++) {
                uint32_t off = a_base[mf] + (kb ^ a_swz[mf]);
                ldmx4(a_h[mf], aHi + off);
                ldmx4(a_l[mf], aLo + off);
            }
            #pragma unroll
            for (int np = 0; np < 2; np++) {
                uint32_t off = b_base[np] + (kb ^ b_swz[np]);
                ldmx4(b_h[np], bHi + off);
                ldmx4(b_l[np], bLo + off);
            }
            #pragma unroll
            for (int mf = 0; mf < 4; mf++) {
                #pragma unroll
                for (int nf = 0; nf < 4; nf++) {
                    int p = nf >> 1, q = nf & 1;
                    mma16816(acc[mf][nf], a_h[mf], b_h[p][q], b_h[p][q + 2]);
                    mma16816(acc[mf][nf], a_h[mf], b_l[p][q], b_l[p][q + 2]);
                    mma16816(acc[mf][nf], a_l[mf], b_h[p][q], b_h[p][q + 2]);
                }
            }
        }
    };

    // ---- 3-stage pipelined main loop (one barrier per chunk) ----
    load_stage(0, 0);
    if (nch > 1) load_stage(1, 1);
    int sidx = 0;
    for (int kc = 0; kc < nch; kc++) {
        if (kc + 1 < nch) { CP_WAIT1(); } else { CP_WAIT0(); }
        __syncthreads();
        if (kc + 2 < nch) {
            int s2 = sidx + 2; if (s2 >= NSTAGE) s2 -= NSTAGE;
            load_stage(s2, kc + 2);
        }
        compute_stage(sidx);
        if (++sidx == NSTAGE) sidx = 0;
    }

    // ---- epilogue ----
    const int qrow = lane >> 2;             // 0..7
    const int c2   = 2 * (lane & 3);        // 0,2,4,6

    if (mode == 0) {
        #pragma unroll
        for (int mf = 0; mf < 4; mf++) {
            size_t r0 = bm + (size_t)(wy * 64 + mf * 16 + qrow);
            #pragma unroll
            for (int nf = 0; nf < 4; nf++) {
                size_t col = bn + (size_t)(wx * 32 + nf * 8 + c2);
                #pragma unroll
                for (int sub = 0; sub < 2; sub++) {
                    size_t r = r0 + sub * 8;
                    float v0 = acc[mf][nf][sub * 2 + 0];
                    float v1 = acc[mf][nf][sub * 2 + 1];
                    h16 h0 = __float2half(v0);
                    h16 h1 = __float2half(v1);
                    h16 l0 = __float2half(v0 - __half2float(h0));
                    h16 l1 = __float2half(v1 - __half2float(h1));
                    __half2 hp; hp.x = h0; hp.y = h1;
                    __half2 lp; lp.x = l0; lp.y = l1;
                    *(__half2*)(oth + r * Ntot + col) = hp;
                    *(__half2*)(otl + r * Ntot + col) = lp;
                }
            }
        }
    } else if (mode == 1) {
        #pragma unroll
        for (int mf = 0; mf < 4; mf++) {
            size_t r0 = bm + (size_t)(wy * 64 + mf * 16 + qrow);
            #pragma unroll
            for (int nf = 0; nf < 4; nf++) {
                size_t col = bn + (size_t)(wx * 32 + nf * 8 + c2);
                float b0 = bias[col], b1 = bias[col + 1];
                #pragma unroll
                for (int sub = 0; sub < 2; sub++) {
                    size_t r = r0 + sub * 8;
                    float2 o;
                    o.x = acc[mf][nf][sub * 2 + 0] + b0;
                    o.y = acc[mf][nf][sub * 2 + 1] + b1;
                    *(float2*)(outf + r * Ntot + col) = o;
                }
            }
        }
    } else {
        // mode 2: fused argmin over scores = csq[c] - 2*acc
        #pragma unroll
        for (int mf = 0; mf < 4; mf++) {
            #pragma unroll
            for (int sub = 0; sub < 2; sub++) {
                unsigned long long best = 0xFFFFFFFFFFFFFFFFull;
                #pragma unroll
                for (int nf = 0; nf < 4; nf++) {
                    int col = (int)bn + wx * 32 + nf * 8 + c2;
                    #pragma unroll
                    for (int j = 0; j < 2; j++) {
                        float s = g_csq[col + j] - 2.0f * acc[mf][nf][sub * 2 + j];
                        unsigned long long key =
                            ((unsigned long long)ford(s) << 32) | (uint32_t)(col + j);
                        if (key < best) best = key;
                    }
                }
                unsigned long long o;
                o = __shfl_down_sync(0xFFFFFFFFu, best, 2);
                if (o < best) best = o;
                o = __shfl_down_sync(0xFFFFFFFFu, best, 1);
                if (o < best) best = o;
                if ((lane & 3) == 0) {
                    size_t row = bm + (size_t)(wy * 64 + mf * 16 + sub * 8 + qrow);
                    atomicMin(&g_key[row], best);
                }
            }
        }
    }
}

// ---------------------------------------------------------------------------
// LayerNorm over D=512, writes fp16 hi/lo split directly.
// ---------------------------------------------------------------------------
__global__ __launch_bounds__(256) void ln_kernel(const float* __restrict__ x,
                                                 const float* __restrict__ gamma,
                                                 const float* __restrict__ beta) {
    int r = blockIdx.x;
    const float* xr = x + (size_t)r * DD;
    int t = threadIdx.x;

    float v0 = xr[t];
    float v1 = xr[t + 256];
    float s  = v0 + v1;
    float ss = v0 * v0 + v1 * v1;

    #pragma unroll
    for (int off = 16; off > 0; off >>= 1) {
        s  += __shfl_down_sync(0xFFFFFFFFu, s,  off);
        ss += __shfl_down_sync(0xFFFFFFFFu, ss, off);
    }
    __shared__ float sh_s[8], sh_ss[8];
    int w = t >> 5, l = t & 31;
    if (l == 0) { sh_s[w] = s; sh_ss[w] = ss; }
    __syncthreads();
    if (t == 0) {
        float S = 0.f, SS = 0.f;
        #pragma unroll
        for (int i = 0; i < 8; i++) { S += sh_s[i]; SS += sh_ss[i]; }
        sh_s[0]  = S * (1.0f / DD);
        sh_ss[0] = SS * (1.0f / DD);
    }
    __syncthreads();
    float mu  = sh_s[0];
    float var = sh_ss[0] - mu * mu;
    float rs  = rsqrtf(var + 1e-5f);

    float y0 = (v0 - mu) * rs * gamma[t]       + beta[t];
    float y1 = (v1 - mu) * rs * gamma[t + 256] + beta[t + 256];

    size_t base = (size_t)r * DD;
    h16 h0 = __float2half(y0);
    h16 h1 = __float2half(y1);
    g_x_hi[base + t]       = h0;
    g_x_hi[base + t + 256] = h1;
    g_x_lo[base + t]       = __float2half(y0 - __half2float(h0));
    g_x_lo[base + t + 256] = __float2half(y1 - __half2float(h1));
}

// ---------------------------------------------------------------------------
// fp32 -> fp16 hi/lo split (weights)
// ---------------------------------------------------------------------------
__global__ __launch_bounds__(256) void split_kernel(const float* __restrict__ src,
                                                    h16* __restrict__ hi,
                                                    h16* __restrict__ lo, int n) {
    int i = blockIdx.x * 256 + threadIdx.x;
    if (i < n) {
        float v = src[i];
        h16 h = __float2half(v);
        hi[i] = h;
        lo[i] = __float2half(v - __half2float(h));
    }
}

// ---------------------------------------------------------------------------
// Codebook transpose + split: cbT[c][q] = split(cb[q][c]). grid (C/32, Q/32)
// ---------------------------------------------------------------------------
__global__ __launch_bounds__(256) void cbt_kernel(const float* __restrict__ cb) {
    __shared__ float t[32][33];
    int c0 = blockIdx.x * 32, q0 = blockIdx.y * 32;
    int tx = threadIdx.x & 31, ty = threadIdx.x >> 5;  // 32 x 8

    #pragma unroll
    for (int r = ty; r < 32; r += 8)
        t[r][tx] = cb[(size_t)(q0 + r) * CC + c0 + tx];
    __syncthreads();
    #pragma unroll
    for (int r = ty; r < 32; r += 8) {
        float v = t[tx][r];   // = cb[q0+tx][c0+r]
        h16 h = __float2half(v);
        size_t idx = (size_t)(c0 + r) * QQ + q0 + tx;
        g_cbt_hi[idx] = h;
        g_cbt_lo[idx] = __float2half(v - __half2float(h));
    }
}

// ---------------------------------------------------------------------------
// c_sq[c] = sum_q cb[q][c]^2
// ---------------------------------------------------------------------------
__global__ __launch_bounds__(256) void csq_kernel(const float* __restrict__ cb) {
    int c = blockIdx.x * 256 + threadIdx.x;
    float s = 0.f;
    #pragma unroll 4
    for (int q = 0; q < QQ; q++) {
        float v = cb[(size_t)q * CC + c];
        s += v * v;
    }
    g_csq[c] = s;
}

// ---------------------------------------------------------------------------
__global__ __launch_bounds__(256) void init_keys() {
    int i = blockIdx.x * 256 + threadIdx.x;
    g_key[i] = 0xFFFFFFFFFFFFFFFFull;
}
__global__ __launch_bounds__(256) void fin_labels(float* __restrict__ labels) {
    int i = blockIdx.x * 256 + threadIdx.x;
    labels[i] = (float)(uint32_t)(g_key[i] & 0xFFFFFFFFull);
}

// ---------------------------------------------------------------------------
extern "C" void kernel_launch(void* const* d_in, const int* in_sizes, int n_in,
                              void* d_out, int out_size) {
    const float* x     = (const float*)d_in[0];
    const float* gamma = (const float*)d_in[1];
    const float* beta  = (const float*)d_in[2];
    const float* projw = (const float*)d_in[3];
    const float* cb    = (const float*)d_in[4];
    const float* encw  = (const float*)d_in[5];
    const float* encb  = (const float*)d_in[6];

    float* out     = (float*)d_out;
    float* enc_out = out;                               // (M, Q) fp32
    float* labels  = out + ((size_t)out_size - MM);     // (M,) as fp32

    h16 *xh, *xl, *th, *tl, *ch, *cl, *pwh, *pwl, *ewh, *ewl;
    cudaGetSymbolAddress((void**)&xh, g_x_hi);
    cudaGetSymbolAddress((void**)&xl, g_x_lo);
    cudaGetSymbolAddress((void**)&th, g_t_hi);
    cudaGetSymbolAddress((void**)&tl, g_t_lo);
    cudaGetSymbolAddress((void**)&ch, g_cbt_hi);
    cudaGetSymbolAddress((void**)&cl, g_cbt_lo);
    cudaGetSymbolAddress((void**)&pwh, g_pw_hi);
    cudaGetSymbolAddress((void**)&pwl, g_pw_lo);
    cudaGetSymbolAddress((void**)&ewh, g_ew_hi);
    cudaGetSymbolAddress((void**)&ewl, g_ew_lo);

    cudaFuncSetAttribute(hgemm_split, cudaFuncAttributeMaxDynamicSharedMemorySize,
                         SMEM_TOTAL);

    // 1) LayerNorm -> fp16 split
    ln_kernel<<<MM, 256>>>(x, gamma, beta);

    // 2) preprocessing
    split_kernel<<<(QQ * DD + 255) / 256, 256>>>(projw, pwh, pwl, QQ * DD);
    split_kernel<<<(QQ * DD + 255) / 256, 256>>>(encw, ewh, ewl, QQ * DD);
    cbt_kernel<<<dim3(CC / 32, QQ / 32), 256>>>(cb);
    csq_kernel<<<CC / 256, 256>>>(cb);
    init_keys<<<MM / 256, 256>>>();

    // 3) targets = xnorm @ proj_w^T  (split fp16 epilogue)
    dim3 grid12(QQ / 128, MM / 128);
    hgemm_split<<<grid12, 256, SMEM_TOTAL>>>(xh, xl, pwh, pwl, DD, QQ, 0,
                                             nullptr, nullptr, th, tl);

    // 4) encoder_out = xnorm @ enc_w^T + enc_b  (fp32 epilogue)
    hgemm_split<<<grid12, 256, SMEM_TOTAL>>>(xh, xl, ewh, ewl, DD, QQ, 1,
                                             encb, enc_out, nullptr, nullptr);

    // 5) cross-GEMM + fused argmin over C
    dim3 gridx(CC / 128, MM / 128);
    hgemm_split<<<gridx, 256, SMEM_TOTAL>>>(th, tl, ch, cl, QQ, CC, 2,
                                            nullptr, nullptr, nullptr, nullptr);

    // 6) finalize labels
    fin_labels<<<MM / 256, 256>>>(labels);

    (void)in_sizes; (void)n_in;
}

// round 5
// speedup vs baseline: 4.3511x; 1.8509x over previous
#include <cuda_runtime.h>
#include <cuda_fp16.h>
#include <math_constants.h>
#include <cstdint>

// Problem constants
#define BB 8
#define TT 8192
#define DD 512
#define QQ 1024
#define CC 4096
#define MM (BB * TT)   // 65536

typedef __half h16;

// ---------------------------------------------------------------------------
// Scratch (__device__ globals; allocation-free rule)
// ---------------------------------------------------------------------------
__device__ __align__(16) h16 g_x_hi[(size_t)MM * DD];
__device__ __align__(16) h16 g_x_lo[(size_t)MM * DD];
__device__ __align__(16) h16 g_w2t_hi[(size_t)CC * DD];   // W2^T [C][D], fp16 split
__device__ __align__(16) h16 g_w2t_lo[(size_t)CC * DD];
__device__ __align__(16) h16 g_ew_hi[(size_t)QQ * DD];
__device__ __align__(16) h16 g_ew_lo[(size_t)QQ * DD];
__device__ float g_csq[CC];
__device__ unsigned long long g_key[MM];

// ---------------------------------------------------------------------------
// PTX helpers (sm_80-class: cp.async / ldmatrix / mma.sync)
// ---------------------------------------------------------------------------
__device__ __forceinline__ uint32_t smem_u32(const void* p) {
    uint32_t a;
    asm("{ .reg .u64 t; cvta.to.shared.u64 t, %1; cvt.u32.u64 %0, t; }"
        : "=r"(a) : "l"(p));
    return a;
}
__device__ __forceinline__ void cp16(uint32_t dst, const void* src) {
    asm volatile("cp.async.cg.shared.global [%0], [%1], 16;" :: "r"(dst), "l"(src));
}
#define CP_COMMIT() asm volatile("cp.async.commit_group;")
#define CP_WAIT1()  asm volatile("cp.async.wait_group 1;")
#define CP_WAIT0()  asm volatile("cp.async.wait_group 0;")

__device__ __forceinline__ void ldmx4(uint32_t* r, uint32_t addr) {
    asm volatile("ldmatrix.sync.aligned.m8n8.x4.shared.b16 {%0,%1,%2,%3}, [%4];"
                 : "=r"(r[0]), "=r"(r[1]), "=r"(r[2]), "=r"(r[3]) : "r"(addr));
}
__device__ __forceinline__ void mma16816(float* d, const uint32_t* a,
                                         uint32_t b0, uint32_t b1) {
    asm volatile("mma.sync.aligned.m16n8k16.row.col.f32.f16.f16.f32 "
                 "{%0,%1,%2,%3}, {%4,%5,%6,%7}, {%8,%9}, {%0,%1,%2,%3};"
                 : "+f"(d[0]), "+f"(d[1]), "+f"(d[2]), "+f"(d[3])
                 : "r"(a[0]), "r"(a[1]), "r"(a[2]), "r"(a[3]), "r"(b0), "r"(b1));
}

// float -> order-preserving uint32 (ascending)
__device__ __forceinline__ uint32_t ford(float s) {
    uint32_t b = __float_as_uint(s);
    return (b & 0x80000000u) ? ~b : (b | 0x80000000u);
}

// ---------------------------------------------------------------------------
// Unified split-fp16 HGEMM: C[M,N] = A(M,K) @ B(N,K)^T via 3-pass hi/lo split.
//   mode 1: write C+bias fp32 to outf                      [encoder_out]
//   mode 2: score = csq[c] - 2*C; atomicMin packed argmin  [labels]
// Tiles: BM=BN=128, BK=64. 256 threads (8 warps, 2x4 warp grid, 64x32/warp).
// 3-stage cp.async pipeline. smem = 192KB.
// ---------------------------------------------------------------------------
#define STG    65536
#define T_AH   0
#define T_AL   16384
#define T_BH   32768
#define T_BL   49152
#define NSTAGE 3
#define SMEM_TOTAL (NSTAGE * STG)

__global__ __launch_bounds__(256, 1) void hgemm_split(
    const h16* __restrict__ Ah, const h16* __restrict__ Al,
    const h16* __restrict__ Bh, const h16* __restrict__ Bl,
    int K, int Ntot, int mode,
    const float* __restrict__ bias,
    float* __restrict__ outf)
{
    extern __shared__ __align__(1024) char smem[];
    const uint32_t sb = smem_u32(smem);
    const int tid  = threadIdx.x;
    const int lane = tid & 31;
    const int wid  = tid >> 5;
    const int wy   = wid >> 2;      // 0..1
    const int wx   = wid & 3;       // 0..3
    const size_t bm = (size_t)blockIdx.y * 128;
    const size_t bn = (size_t)blockIdx.x * 128;

    float acc[4][4][4];
    #pragma unroll
    for (int i = 0; i < 4; i++)
        #pragma unroll
        for (int j = 0; j < 4; j++)
            #pragma unroll
            for (int k = 0; k < 4; k++) acc[i][j][k] = 0.f;

    // loader lane mapping: row = tid>>1 (0..127), half = tid&1 (64B each)
    const int lrow  = tid >> 1;
    const int lhalf = tid & 1;
    const uint32_t swr   = (uint32_t)((lrow & 7) << 4);
    const uint32_t rbase = (uint32_t)(lrow * 128);

    const char* pAh = (const char*)(Ah + (bm + lrow) * (size_t)K);
    const char* pAl = (const char*)(Al + (bm + lrow) * (size_t)K);
    const char* pBh = (const char*)(Bh + (bn + lrow) * (size_t)K);
    const char* pBl = (const char*)(Bl + (bn + lrow) * (size_t)K);

    const int nch = K >> 6;

    auto load_stage = [&](int s, int kc) {
        uint32_t st = sb + (uint32_t)s * STG;
        int kbyte0 = kc << 7;                        // kc*64 elems * 2B
        #pragma unroll
        for (int i = 0; i < 4; i++) {
            uint32_t ko = (uint32_t)(lhalf * 64 + i * 16);
            uint32_t d  = rbase + (ko ^ swr);
            cp16(st + T_AH + d, pAh + kbyte0 + ko);
            cp16(st + T_AL + d, pAl + kbyte0 + ko);
            cp16(st + T_BH + d, pBh + kbyte0 + ko);
            cp16(st + T_BL + d, pBl + kbyte0 + ko);
        }
        CP_COMMIT();
    };

    // precomputed fragment addresses (k-independent parts)
    const int rl  = lane & 15;
    const uint32_t kbh = (uint32_t)((lane >> 4) << 4);
    uint32_t a_base[4], a_swz[4], b_base[2], b_swz[2];
    #pragma unroll
    for (int mf = 0; mf < 4; mf++) {
        int r = wy * 64 + mf * 16 + rl;
        a_base[mf] = (uint32_t)(r * 128);
        a_swz[mf]  = (uint32_t)((r & 7) << 4);
    }
    #pragma unroll
    for (int np = 0; np < 2; np++) {
        int n = wx * 32 + np * 16 + rl;
        b_base[np] = (uint32_t)(n * 128);
        b_swz[np]  = (uint32_t)((n & 7) << 4);
    }

    auto compute_stage = [&](int s) {
        uint32_t base = sb + (uint32_t)s * STG;
        uint32_t aHi = base + T_AH, aLo = base + T_AL;
        uint32_t bHi = base + T_BH, bLo = base + T_BL;

        #pragma unroll
        for (int ks = 0; ks < 4; ks++) {
            uint32_t kb = (uint32_t)(ks * 32) + kbh;
            uint32_t a_h[4][4], a_l[4][4], b_h[2][4], b_l[2][4];
            #pragma unroll
            for (int mf = 0; mf < 4; mf++) {
                uint32_t off = a_base[mf] + (kb ^ a_swz[mf]);
                ldmx4(a_h[mf], aHi + off);
                ldmx4(a_l[mf], aLo + off);
            }
            #pragma unroll
            for (int np = 0; np < 2; np++) {
                uint32_t off = b_base[np] + (kb ^ b_swz[np]);
                ldmx4(b_h[np], bHi + off);
                ldmx4(b_l[np], bLo + off);
            }
            #pragma unroll
            for (int mf = 0; mf < 4; mf++) {
                #pragma unroll
                for (int nf = 0; nf < 4; nf++) {
                    int p = nf >> 1, q = nf & 1;
                    mma16816(acc[mf][nf], a_h[mf], b_h[p][q], b_h[p][q + 2]);
                    mma16816(acc[mf][nf], a_h[mf], b_l[p][q], b_l[p][q + 2]);
                    mma16816(acc[mf][nf], a_l[mf], b_h[p][q], b_h[p][q + 2]);
                }
            }
        }
    };

    // 3-stage pipelined main loop
    load_stage(0, 0);
    if (nch > 1) load_stage(1, 1);
    int sidx = 0;
    for (int kc = 0; kc < nch; kc++) {
        if (kc + 1 < nch) { CP_WAIT1(); } else { CP_WAIT0(); }
        __syncthreads();
        if (kc + 2 < nch) {
            int s2 = sidx + 2; if (s2 >= NSTAGE) s2 -= NSTAGE;
            load_stage(s2, kc + 2);
        }
        compute_stage(sidx);
        if (++sidx == NSTAGE) sidx = 0;
    }

    // epilogue
    const int qrow = lane >> 2;             // 0..7
    const int c2   = 2 * (lane & 3);        // 0,2,4,6

    if (mode == 1) {
        #pragma unroll
        for (int mf = 0; mf < 4; mf++) {
            size_t r0 = bm + (size_t)(wy * 64 + mf * 16 + qrow);
            #pragma unroll
            for (int nf = 0; nf < 4; nf++) {
                size_t col = bn + (size_t)(wx * 32 + nf * 8 + c2);
                float b0 = bias[col], b1 = bias[col + 1];
                #pragma unroll
                for (int sub = 0; sub < 2; sub++) {
                    size_t r = r0 + sub * 8;
                    float2 o;
                    o.x = acc[mf][nf][sub * 2 + 0] + b0;
                    o.y = acc[mf][nf][sub * 2 + 1] + b1;
                    *(float2*)(outf + r * Ntot + col) = o;
                }
            }
        }
    } else {
        // mode 2: fused argmin over scores = csq[c] - 2*acc
        #pragma unroll
        for (int mf = 0; mf < 4; mf++) {
            #pragma unroll
            for (int sub = 0; sub < 2; sub++) {
                unsigned long long best = 0xFFFFFFFFFFFFFFFFull;
                #pragma unroll
                for (int nf = 0; nf < 4; nf++) {
                    int col = (int)bn + wx * 32 + nf * 8 + c2;
                    #pragma unroll
                    for (int j = 0; j < 2; j++) {
                        float s = g_csq[col + j] - 2.0f * acc[mf][nf][sub * 2 + j];
                        unsigned long long key =
                            ((unsigned long long)ford(s) << 32) | (uint32_t)(col + j);
                        if (key < best) best = key;
                    }
                }
                unsigned long long o;
                o = __shfl_down_sync(0xFFFFFFFFu, best, 2);
                if (o < best) best = o;
                o = __shfl_down_sync(0xFFFFFFFFu, best, 1);
                if (o < best) best = o;
                if ((lane & 3) == 0) {
                    size_t row = bm + (size_t)(wy * 64 + mf * 16 + sub * 8 + qrow);
                    atomicMin(&g_key[row], best);
                }
            }
        }
    }
}

// ---------------------------------------------------------------------------
// W2^T precompute: W2T[c][d] = sum_q cb[q][c] * projw[q][d], fp32 SIMT,
// split epilogue to fp16 hi/lo. 128x128 tiles, grid (C/128, D/128).
// ---------------------------------------------------------------------------
__global__ __launch_bounds__(256) void w2t_kernel(const float* __restrict__ projw,
                                                  const float* __restrict__ cb) {
    __shared__ __align__(16) float As[8][128];   // cb chunk: [q][c]
    __shared__ __align__(16) float Bs[8][128];   // projw chunk: [q][d]

    int tid = threadIdx.x;
    int c0 = blockIdx.x * 128;
    int d0 = blockIdx.y * 128;

    int lr = tid >> 5;            // 0..7 (q row)
    int lc = (tid & 31) * 4;      // 0..124

    int ty = tid >> 4;            // 0..15 (c group)
    int tx = tid & 15;            // 0..15 (d group)

    float acc[8][8];
    #pragma unroll
    for (int i = 0; i < 8; i++)
        #pragma unroll
        for (int j = 0; j < 8; j++) acc[i][j] = 0.f;

    for (int k0 = 0; k0 < QQ; k0 += 8) {
        *(float4*)&As[lr][lc] = *(const float4*)(cb + (size_t)(k0 + lr) * CC + c0 + lc);
        *(float4*)&Bs[lr][lc] = *(const float4*)(projw + (size_t)(k0 + lr) * DD + d0 + lc);
        __syncthreads();
        #pragma unroll
        for (int k = 0; k < 8; k++) {
            float ar[8], br[8];
            float4 a0 = *(const float4*)&As[k][ty * 8];
            float4 a1 = *(const float4*)&As[k][ty * 8 + 4];
            float4 b0 = *(const float4*)&Bs[k][tx * 8];
            float4 b1 = *(const float4*)&Bs[k][tx * 8 + 4];
            ar[0]=a0.x; ar[1]=a0.y; ar[2]=a0.z; ar[3]=a0.w;
            ar[4]=a1.x; ar[5]=a1.y; ar[6]=a1.z; ar[7]=a1.w;
            br[0]=b0.x; br[1]=b0.y; br[2]=b0.z; br[3]=b0.w;
            br[4]=b1.x; br[5]=b1.y; br[6]=b1.z; br[7]=b1.w;
            #pragma unroll
            for (int i = 0; i < 8; i++)
                #pragma unroll
                for (int j = 0; j < 8; j++)
                    acc[i][j] = fmaf(ar[i], br[j], acc[i][j]);
        }
        __syncthreads();
    }

    #pragma unroll
    for (int i = 0; i < 8; i++) {
        size_t row = (size_t)(c0 + ty * 8 + i) * DD + d0 + tx * 8;
        #pragma unroll
        for (int j = 0; j < 8; j++) {
            float v = acc[i][j];
            h16 h = __float2half(v);
            g_w2t_hi[row + j] = h;
            g_w2t_lo[row + j] = __float2half(v - __half2float(h));
        }
    }
}

// ---------------------------------------------------------------------------
// LayerNorm over D=512, writes fp16 hi/lo split directly.
// ---------------------------------------------------------------------------
__global__ __launch_bounds__(256) void ln_kernel(const float* __restrict__ x,
                                                 const float* __restrict__ gamma,
                                                 const float* __restrict__ beta) {
    int r = blockIdx.x;
    const float* xr = x + (size_t)r * DD;
    int t = threadIdx.x;

    float v0 = xr[t];
    float v1 = xr[t + 256];
    float s  = v0 + v1;
    float ss = v0 * v0 + v1 * v1;

    #pragma unroll
    for (int off = 16; off > 0; off >>= 1) {
        s  += __shfl_down_sync(0xFFFFFFFFu, s,  off);
        ss += __shfl_down_sync(0xFFFFFFFFu, ss, off);
    }
    __shared__ float sh_s[8], sh_ss[8];
    int w = t >> 5, l = t & 31;
    if (l == 0) { sh_s[w] = s; sh_ss[w] = ss; }
    __syncthreads();
    if (t == 0) {
        float S = 0.f, SS = 0.f;
        #pragma unroll
        for (int i = 0; i < 8; i++) { S += sh_s[i]; SS += sh_ss[i]; }
        sh_s[0]  = S * (1.0f / DD);
        sh_ss[0] = SS * (1.0f / DD);
    }
    __syncthreads();
    float mu  = sh_s[0];
    float var = sh_ss[0] - mu * mu;
    float rs  = rsqrtf(var + 1e-5f);

    float y0 = (v0 - mu) * rs * gamma[t]       + beta[t];
    float y1 = (v1 - mu) * rs * gamma[t + 256] + beta[t + 256];

    size_t base = (size_t)r * DD;
    h16 h0 = __float2half(y0);
    h16 h1 = __float2half(y1);
    g_x_hi[base + t]       = h0;
    g_x_hi[base + t + 256] = h1;
    g_x_lo[base + t]       = __float2half(y0 - __half2float(h0));
    g_x_lo[base + t + 256] = __float2half(y1 - __half2float(h1));
}

// ---------------------------------------------------------------------------
// fp32 -> fp16 hi/lo split (weights)
// ---------------------------------------------------------------------------
__global__ __launch_bounds__(256) void split_kernel(const float* __restrict__ src,
                                                    h16* __restrict__ hi,
                                                    h16* __restrict__ lo, int n) {
    int i = blockIdx.x * 256 + threadIdx.x;
    if (i < n) {
        float v = src[i];
        h16 h = __float2half(v);
        hi[i] = h;
        lo[i] = __float2half(v - __half2float(h));
    }
}

// ---------------------------------------------------------------------------
// c_sq[c] = sum_q cb[q][c]^2
// ---------------------------------------------------------------------------
__global__ __launch_bounds__(256) void csq_kernel(const float* __restrict__ cb) {
    int c = blockIdx.x * 256 + threadIdx.x;
    float s = 0.f;
    #pragma unroll 4
    for (int q = 0; q < QQ; q++) {
        float v = cb[(size_t)q * CC + c];
        s += v * v;
    }
    g_csq[c] = s;
}

// ---------------------------------------------------------------------------
__global__ __launch_bounds__(256) void init_keys() {
    int i = blockIdx.x * 256 + threadIdx.x;
    g_key[i] = 0xFFFFFFFFFFFFFFFFull;
}
__global__ __launch_bounds__(256) void fin_labels(float* __restrict__ labels) {
    int i = blockIdx.x * 256 + threadIdx.x;
    labels[i] = (float)(uint32_t)(g_key[i] & 0xFFFFFFFFull);
}

// ---------------------------------------------------------------------------
extern "C" void kernel_launch(void* const* d_in, const int* in_sizes, int n_in,
                              void* d_out, int out_size) {
    const float* x     = (const float*)d_in[0];
    const float* gamma = (const float*)d_in[1];
    const float* beta  = (const float*)d_in[2];
    const float* projw = (const float*)d_in[3];
    const float* cb    = (const float*)d_in[4];
    const float* encw  = (const float*)d_in[5];
    const float* encb  = (const float*)d_in[6];

    float* out     = (float*)d_out;
    float* enc_out = out;                               // (M, Q) fp32
    float* labels  = out + ((size_t)out_size - MM);     // (M,) as fp32

    h16 *xh, *xl, *w2h, *w2l, *ewh, *ewl;
    cudaGetSymbolAddress((void**)&xh, g_x_hi);
    cudaGetSymbolAddress((void**)&xl, g_x_lo);
    cudaGetSymbolAddress((void**)&w2h, g_w2t_hi);
    cudaGetSymbolAddress((void**)&w2l, g_w2t_lo);
    cudaGetSymbolAddress((void**)&ewh, g_ew_hi);
    cudaGetSymbolAddress((void**)&ewl, g_ew_lo);

    cudaFuncSetAttribute(hgemm_split, cudaFuncAttributeMaxDynamicSharedMemorySize,
                         SMEM_TOTAL);

    // 1) LayerNorm -> fp16 split
    ln_kernel<<<MM, 256>>>(x, gamma, beta);

    // 2) preprocessing: enc_w split, fused codebook matrix W2^T, csq, keys
    split_kernel<<<(QQ * DD + 255) / 256, 256>>>(encw, ewh, ewl, QQ * DD);
    w2t_kernel<<<dim3(CC / 128, DD / 128), 256>>>(projw, cb);
    csq_kernel<<<CC / 256, 256>>>(cb);
    init_keys<<<MM / 256, 256>>>();

    // 3) encoder_out = xnorm @ enc_w^T + enc_b  (fp32 epilogue), K=512
    dim3 grid12(QQ / 128, MM / 128);
    hgemm_split<<<grid12, 256, SMEM_TOTAL>>>(xh, xl, ewh, ewl, DD, QQ, 1,
                                             encb, enc_out);

    // 4) cross-GEMM + fused argmin: scores = csq - 2 * (xnorm @ W2T^T), K=512
    dim3 gridx(CC / 128, MM / 128);
    hgemm_split<<<gridx, 256, SMEM_TOTAL>>>(xh, xl, w2h, w2l, DD, CC, 2,
                                            nullptr, nullptr);

    // 5) finalize labels
    fin_labels<<<MM / 256, 256>>>(labels);

    (void)in_sizes; (void)n_in;
}

// round 6
// speedup vs baseline: 8.1811x; 1.8802x over previous
#include <cuda_runtime.h>
#include <cuda_fp16.h>
#include <math_constants.h>
#include <cstdint>

// Problem constants
#define BB 8
#define TT 8192
#define DD 512
#define QQ 1024
#define CC 4096
#define MM (BB * TT)   // 65536

typedef __half h16;

// ---------------------------------------------------------------------------
// Scratch (__device__ globals; allocation-free rule)
// ---------------------------------------------------------------------------
__device__ __align__(16) h16 g_x_hi[(size_t)MM * DD];
__device__ __align__(16) h16 g_x_lo[(size_t)MM * DD];
__device__ __align__(16) h16 g_w2t_hi[(size_t)CC * DD];   // W2^T [C][D]
__device__ __align__(16) h16 g_w2t_lo[(size_t)CC * DD];
__device__ __align__(16) h16 g_ew_hi[(size_t)QQ * DD];
__device__ __align__(16) h16 g_sc[(size_t)MM * CC];       // approx scores (512 MB)
__device__ float g_csq[CC];
__device__ unsigned long long g_key[MM];

// ---------------------------------------------------------------------------
// PTX helpers
// ---------------------------------------------------------------------------
__device__ __forceinline__ uint32_t smem_u32(const void* p) {
    uint32_t a;
    asm("{ .reg .u64 t; cvta.to.shared.u64 t, %1; cvt.u32.u64 %0, t; }"
        : "=r"(a) : "l"(p));
    return a;
}
__device__ __forceinline__ void cp16(uint32_t dst, const void* src) {
    asm volatile("cp.async.cg.shared.global [%0], [%1], 16;" :: "r"(dst), "l"(src));
}
#define CP_COMMIT() asm volatile("cp.async.commit_group;")
#define CP_WAIT1()  asm volatile("cp.async.wait_group 1;")
#define CP_WAIT0()  asm volatile("cp.async.wait_group 0;")

__device__ __forceinline__ void ldmx4(uint32_t* r, uint32_t addr) {
    asm volatile("ldmatrix.sync.aligned.m8n8.x4.shared.b16 {%0,%1,%2,%3}, [%4];"
                 : "=r"(r[0]), "=r"(r[1]), "=r"(r[2]), "=r"(r[3]) : "r"(addr));
}
__device__ __forceinline__ void mma16816(float* d, const uint32_t* a,
                                         uint32_t b0, uint32_t b1) {
    asm volatile("mma.sync.aligned.m16n8k16.row.col.f32.f16.f16.f32 "
                 "{%0,%1,%2,%3}, {%4,%5,%6,%7}, {%8,%9}, {%0,%1,%2,%3};"
                 : "+f"(d[0]), "+f"(d[1]), "+f"(d[2]), "+f"(d[3])
                 : "r"(a[0]), "r"(a[1]), "r"(a[2]), "r"(a[3]), "r"(b0), "r"(b1));
}

// float <-> order-preserving uint32 (ascending)
__device__ __forceinline__ uint32_t ford(float s) {
    uint32_t b = __float_as_uint(s);
    return (b & 0x80000000u) ? ~b : (b | 0x80000000u);
}
__device__ __forceinline__ float unford(uint32_t f) {
    uint32_t b = (f & 0x80000000u) ? (f & 0x7FFFFFFFu) : ~f;
    return __uint_as_float(b);
}

// ---------------------------------------------------------------------------
// 1-pass HGEMM: C[M,N] = Ah(M,K) @ Bh(N,K)^T (hi parts only).
//   MODE 1: write C+bias fp32 to outf                          [encoder_out]
//   MODE 2: score = csq[c] - 2*C; store fp16 score + atomicMin [label screen]
// BM=BN=128, BK=64, 256 threads (2x4 warps, 64x32 warp tile),
// 3-stage cp.async, 2 streams -> 96KB smem, 2 CTAs/SM.
// ---------------------------------------------------------------------------
#define T_A    0
#define T_B    16384
#define STG1   32768
#define NSTAGE 3
#define SMEM_TOTAL (NSTAGE * STG1)

template<int MODE>
__global__ __launch_bounds__(256, 2) void hgemm1p(
    const h16* __restrict__ A, const h16* __restrict__ B,
    int K, int Ntot,
    const float* __restrict__ bias, float* __restrict__ outf)
{
    extern __shared__ __align__(1024) char smem[];
    const uint32_t sb = smem_u32(smem);
    const int tid  = threadIdx.x;
    const int lane = tid & 31;
    const int wid  = tid >> 5;
    const int wy   = wid >> 2;      // 0..1
    const int wx   = wid & 3;       // 0..3
    const size_t bm = (size_t)blockIdx.y * 128;
    const size_t bn = (size_t)blockIdx.x * 128;

    float acc[4][4][4];
    #pragma unroll
    for (int i = 0; i < 4; i++)
        #pragma unroll
        for (int j = 0; j < 4; j++)
            #pragma unroll
            for (int k = 0; k < 4; k++) acc[i][j][k] = 0.f;

    const int lrow  = tid >> 1;
    const int lhalf = tid & 1;
    const uint32_t swr   = (uint32_t)((lrow & 7) << 4);
    const uint32_t rbase = (uint32_t)(lrow * 128);

    const char* pA = (const char*)(A + (bm + lrow) * (size_t)K);
    const char* pB = (const char*)(B + (bn + lrow) * (size_t)K);

    const int nch = K >> 6;

    auto load_stage = [&](int s, int kc) {
        uint32_t st = sb + (uint32_t)s * STG1;
        int kbyte0 = kc << 7;
        #pragma unroll
        for (int i = 0; i < 4; i++) {
            uint32_t ko = (uint32_t)(lhalf * 64 + i * 16);
            uint32_t d  = rbase + (ko ^ swr);
            cp16(st + T_A + d, pA + kbyte0 + ko);
            cp16(st + T_B + d, pB + kbyte0 + ko);
        }
        CP_COMMIT();
    };

    const int rl  = lane & 15;
    const uint32_t kbh = (uint32_t)((lane >> 4) << 4);
    uint32_t a_base[4], a_swz[4], b_base[2], b_swz[2];
    #pragma unroll
    for (int mf = 0; mf < 4; mf++) {
        int r = wy * 64 + mf * 16 + rl;
        a_base[mf] = (uint32_t)(r * 128);
        a_swz[mf]  = (uint32_t)((r & 7) << 4);
    }
    #pragma unroll
    for (int np = 0; np < 2; np++) {
        int n = wx * 32 + np * 16 + rl;
        b_base[np] = (uint32_t)(n * 128);
        b_swz[np]  = (uint32_t)((n & 7) << 4);
    }

    auto compute_stage = [&](int s) {
        uint32_t base = sb + (uint32_t)s * STG1;
        uint32_t aP = base + T_A, bP = base + T_B;
        #pragma unroll
        for (int ks = 0; ks < 4; ks++) {
            uint32_t kb = (uint32_t)(ks * 32) + kbh;
            uint32_t a_h[4][4], b_h[2][4];
            #pragma unroll
            for (int mf = 0; mf < 4; mf++)
                ldmx4(a_h[mf], aP + a_base[mf] + (kb ^ a_swz[mf]));
            #pragma unroll
            for (int np = 0; np < 2; np++)
                ldmx4(b_h[np], bP + b_base[np] + (kb ^ b_swz[np]));
            #pragma unroll
            for (int mf = 0; mf < 4; mf++)
                #pragma unroll
                for (int nf = 0; nf < 4; nf++) {
                    int p = nf >> 1, q = nf & 1;
                    mma16816(acc[mf][nf], a_h[mf], b_h[p][q], b_h[p][q + 2]);
                }
        }
    };

    load_stage(0, 0);
    if (nch > 1) load_stage(1, 1);
    int sidx = 0;
    for (int kc = 0; kc < nch; kc++) {
        if (kc + 1 < nch) { CP_WAIT1(); } else { CP_WAIT0(); }
        __syncthreads();
        if (kc + 2 < nch) {
            int s2 = sidx + 2; if (s2 >= NSTAGE) s2 -= NSTAGE;
            load_stage(s2, kc + 2);
        }
        compute_stage(sidx);
        if (++sidx == NSTAGE) sidx = 0;
    }

    const int qrow = lane >> 2;
    const int c2   = 2 * (lane & 3);

    if (MODE == 1) {
        #pragma unroll
        for (int mf = 0; mf < 4; mf++) {
            size_t r0 = bm + (size_t)(wy * 64 + mf * 16 + qrow);
            #pragma unroll
            for (int nf = 0; nf < 4; nf++) {
                size_t col = bn + (size_t)(wx * 32 + nf * 8 + c2);
                float b0 = bias[col], b1 = bias[col + 1];
                #pragma unroll
                for (int sub = 0; sub < 2; sub++) {
                    size_t r = r0 + sub * 8;
                    float2 o;
                    o.x = acc[mf][nf][sub * 2 + 0] + b0;
                    o.y = acc[mf][nf][sub * 2 + 1] + b1;
                    *(float2*)(outf + r * Ntot + col) = o;
                }
            }
        }
    } else {
        // MODE 2: approx scores -> fp16 store (streaming) + per-row atomicMin
        #pragma unroll
        for (int mf = 0; mf < 4; mf++) {
            #pragma unroll
            for (int sub = 0; sub < 2; sub++) {
                size_t row = bm + (size_t)(wy * 64 + mf * 16 + sub * 8 + qrow);
                unsigned long long best = 0xFFFFFFFFFFFFFFFFull;
                #pragma unroll
                for (int nf = 0; nf < 4; nf++) {
                    int col = (int)bn + wx * 32 + nf * 8 + c2;
                    float s0 = g_csq[col]     - 2.0f * acc[mf][nf][sub * 2 + 0];
                    float s1 = g_csq[col + 1] - 2.0f * acc[mf][nf][sub * 2 + 1];
                    __half2 hp = __floats2half2_rn(s0, s1);
                    uint32_t u; *(__half2*)&u = hp;
                    __stcs((uint32_t*)(g_sc + row * CC + col), u);
                    unsigned long long k0 =
                        ((unsigned long long)ford(s0) << 32) | (uint32_t)col;
                    unsigned long long k1 =
                        ((unsigned long long)ford(s1) << 32) | (uint32_t)(col + 1);
                    if (k0 < best) best = k0;
                    if (k1 < best) best = k1;
                }
                unsigned long long o;
                o = __shfl_down_sync(0xFFFFFFFFu, best, 2);
                if (o < best) best = o;
                o = __shfl_down_sync(0xFFFFFFFFu, best, 1);
                if (o < best) best = o;
                if ((lane & 3) == 0) atomicMin(&g_key[row], best);
            }
        }
    }
}

// ---------------------------------------------------------------------------
// Refine: per row, candidates = { c : sc16[c] <= approx_min + MARGIN },
// recompute exactly in fp32 (hi+lo reconstruction), argmin w/ low-index ties.
// One warp per row. MARGIN covers approx error (<=0.1 stat, 190 sigma) +
// fp16 quantization (ulp <= 1.0 at |score|~1024).
// ---------------------------------------------------------------------------
#define MARGIN 3.0f

__global__ __launch_bounds__(256) void refine_kernel(float* __restrict__ labels) {
    int warp = blockIdx.x * 8 + (threadIdx.x >> 5);
    int lane = threadIdx.x & 31;
    size_t row = (size_t)warp;

    float amin  = unford((uint32_t)(g_key[row] >> 32));
    float thresh = amin + MARGIN;

    const h16* sr = g_sc + row * CC;
    float best = CUDART_INF_F;
    int bestc = 0;

    for (int base = 0; base < CC; base += 32) {
        float s = __half2float(sr[base + lane]);
        uint32_t mask = __ballot_sync(0xFFFFFFFFu, s <= thresh);
        while (mask) {
            int bit = __ffs(mask) - 1;
            mask &= mask - 1;
            int c = base + bit;
            // warp-cooperative exact dot over D=512
            const h16* xh = g_x_hi + row * DD;
            const h16* xl = g_x_lo + row * DD;
            const h16* wh = g_w2t_hi + (size_t)c * DD;
            const h16* wl = g_w2t_lo + (size_t)c * DD;
            float dot = 0.f;
            #pragma unroll
            for (int j = 0; j < 16; j++) {
                int d = lane + 32 * j;
                float a = __half2float(xh[d]) + __half2float(xl[d]);
                float b = __half2float(wh[d]) + __half2float(wl[d]);
                dot = fmaf(a, b, dot);
            }
            #pragma unroll
            for (int off = 16; off > 0; off >>= 1)
                dot += __shfl_down_sync(0xFFFFFFFFu, dot, off);
            if (lane == 0) {
                float sc = g_csq[c] - 2.0f * dot;
                if (sc < best || (sc == best && c < bestc)) { best = sc; bestc = c; }
            }
        }
    }
    if (lane == 0) labels[row] = (float)bestc;
}

// ---------------------------------------------------------------------------
// W2^T precompute: W2T[c][d] = sum_q cb[q][c]*projw[q][d], fp32, split fp16.
// ---------------------------------------------------------------------------
__global__ __launch_bounds__(256) void w2t_kernel(const float* __restrict__ projw,
                                                  const float* __restrict__ cb) {
    __shared__ __align__(16) float As[8][128];
    __shared__ __align__(16) float Bs[8][128];

    int tid = threadIdx.x;
    int c0 = blockIdx.x * 128;
    int d0 = blockIdx.y * 128;
    int lr = tid >> 5, lc = (tid & 31) * 4;
    int ty = tid >> 4, tx = tid & 15;

    float acc[8][8];
    #pragma unroll
    for (int i = 0; i < 8; i++)
        #pragma unroll
        for (int j = 0; j < 8; j++) acc[i][j] = 0.f;

    for (int k0 = 0; k0 < QQ; k0 += 8) {
        *(float4*)&As[lr][lc] = *(const float4*)(cb + (size_t)(k0 + lr) * CC + c0 + lc);
        *(float4*)&Bs[lr][lc] = *(const float4*)(projw + (size_t)(k0 + lr) * DD + d0 + lc);
        __syncthreads();
        #pragma unroll
        for (int k = 0; k < 8; k++) {
            float ar[8], br[8];
            float4 a0 = *(const float4*)&As[k][ty * 8];
            float4 a1 = *(const float4*)&As[k][ty * 8 + 4];
            float4 b0 = *(const float4*)&Bs[k][tx * 8];
            float4 b1 = *(const float4*)&Bs[k][tx * 8 + 4];
            ar[0]=a0.x; ar[1]=a0.y; ar[2]=a0.z; ar[3]=a0.w;
            ar[4]=a1.x; ar[5]=a1.y; ar[6]=a1.z; ar[7]=a1.w;
            br[0]=b0.x; br[1]=b0.y; br[2]=b0.z; br[3]=b0.w;
            br[4]=b1.x; br[5]=b1.y; br[6]=b1.z; br[7]=b1.w;
            #pragma unroll
            for (int i = 0; i < 8; i++)
                #pragma unroll
                for (int j = 0; j < 8; j++)
                    acc[i][j] = fmaf(ar[i], br[j], acc[i][j]);
        }
        __syncthreads();
    }

    #pragma unroll
    for (int i = 0; i < 8; i++) {
        size_t rowo = (size_t)(c0 + ty * 8 + i) * DD + d0 + tx * 8;
        #pragma unroll
        for (int j = 0; j < 8; j++) {
            float v = acc[i][j];
            h16 h = __float2half(v);
            g_w2t_hi[rowo + j] = h;
            g_w2t_lo[rowo + j] = __float2half(v - __half2float(h));
        }
    }
}

// ---------------------------------------------------------------------------
// LayerNorm over D=512, writes fp16 hi/lo split.
// ---------------------------------------------------------------------------
__global__ __launch_bounds__(256) void ln_kernel(const float* __restrict__ x,
                                                 const float* __restrict__ gamma,
                                                 const float* __restrict__ beta) {
    int r = blockIdx.x;
    const float* xr = x + (size_t)r * DD;
    int t = threadIdx.x;

    float v0 = xr[t], v1 = xr[t + 256];
    float s = v0 + v1, ss = v0 * v0 + v1 * v1;
    #pragma unroll
    for (int off = 16; off > 0; off >>= 1) {
        s  += __shfl_down_sync(0xFFFFFFFFu, s,  off);
        ss += __shfl_down_sync(0xFFFFFFFFu, ss, off);
    }
    __shared__ float sh_s[8], sh_ss[8];
    int w = t >> 5, l = t & 31;
    if (l == 0) { sh_s[w] = s; sh_ss[w] = ss; }
    __syncthreads();
    if (t == 0) {
        float S = 0.f, SS = 0.f;
        #pragma unroll
        for (int i = 0; i < 8; i++) { S += sh_s[i]; SS += sh_ss[i]; }
        sh_s[0]  = S * (1.0f / DD);
        sh_ss[0] = SS * (1.0f / DD);
    }
    __syncthreads();
    float mu = sh_s[0];
    float rs = rsqrtf(sh_ss[0] - mu * mu + 1e-5f);

    float y0 = (v0 - mu) * rs * gamma[t]       + beta[t];
    float y1 = (v1 - mu) * rs * gamma[t + 256] + beta[t + 256];

    size_t base = (size_t)r * DD;
    h16 h0 = __float2half(y0), h1 = __float2half(y1);
    g_x_hi[base + t]       = h0;
    g_x_hi[base + t + 256] = h1;
    g_x_lo[base + t]       = __float2half(y0 - __half2float(h0));
    g_x_lo[base + t + 256] = __float2half(y1 - __half2float(h1));
}

// ---------------------------------------------------------------------------
__global__ __launch_bounds__(256) void split_hi_kernel(const float* __restrict__ src,
                                                       h16* __restrict__ hi, int n) {
    int i = blockIdx.x * 256 + threadIdx.x;
    if (i < n) hi[i] = __float2half(src[i]);
}

// csq: grid (CC/256, 16); partial sums over q, atomicAdd.
__global__ __launch_bounds__(256) void csq_kernel(const float* __restrict__ cb) {
    int c  = blockIdx.x * 256 + threadIdx.x;
    int q0 = blockIdx.y * (QQ / 16);
    float s = 0.f;
    #pragma unroll 4
    for (int q = q0; q < q0 + QQ / 16; q++) {
        float v = cb[(size_t)q * CC + c];
        s += v * v;
    }
    atomicAdd(&g_csq[c], s);
}

__global__ __launch_bounds__(256) void init_kernel() {
    int i = blockIdx.x * 256 + threadIdx.x;
    g_key[i] = 0xFFFFFFFFFFFFFFFFull;
    if (i < CC) g_csq[i] = 0.f;
}

// ---------------------------------------------------------------------------
extern "C" void kernel_launch(void* const* d_in, const int* in_sizes, int n_in,
                              void* d_out, int out_size) {
    const float* x     = (const float*)d_in[0];
    const float* gamma = (const float*)d_in[1];
    const float* beta  = (const float*)d_in[2];
    const float* projw = (const float*)d_in[3];
    const float* cb    = (const float*)d_in[4];
    const float* encw  = (const float*)d_in[5];
    const float* encb  = (const float*)d_in[6];

    float* out     = (float*)d_out;
    float* enc_out = out;                               // (M, Q) fp32
    float* labels  = out + ((size_t)out_size - MM);     // (M,) as fp32

    h16 *xh, *w2h, *ewh;
    cudaGetSymbolAddress((void**)&xh, g_x_hi);
    cudaGetSymbolAddress((void**)&w2h, g_w2t_hi);
    cudaGetSymbolAddress((void**)&ewh, g_ew_hi);

    cudaFuncSetAttribute(hgemm1p<1>, cudaFuncAttributeMaxDynamicSharedMemorySize,
                         SMEM_TOTAL);
    cudaFuncSetAttribute(hgemm1p<2>, cudaFuncAttributeMaxDynamicSharedMemorySize,
                         SMEM_TOTAL);

    // 1) LayerNorm -> fp16 split
    ln_kernel<<<MM, 256>>>(x, gamma, beta);

    // 2) preprocessing
    split_hi_kernel<<<(QQ * DD + 255) / 256, 256>>>(encw, ewh, QQ * DD);
    w2t_kernel<<<dim3(CC / 128, DD / 128), 256>>>(projw, cb);
    init_kernel<<<MM / 256, 256>>>();
    csq_kernel<<<dim3(CC / 256, 16), 256>>>(cb);

    // 3) encoder_out = xnorm @ enc_w^T + enc_b  (1-pass hi GEMM)
    dim3 grid12(QQ / 128, MM / 128);
    hgemm1p<1><<<grid12, 256, SMEM_TOTAL>>>(xh, ewh, DD, QQ, encb, enc_out);

    // 4) label screen: approx scores + per-row approx min (1-pass hi GEMM)
    dim3 gridx(CC / 128, MM / 128);
    hgemm1p<2><<<gridx, 256, SMEM_TOTAL>>>(xh, w2h, DD, CC, nullptr, nullptr);

    // 5) exact refinement of candidates -> labels
    refine_kernel<<<MM / 8, 256>>>(labels);

    (void)in_sizes; (void)n_in;
}

// round 7
// speedup vs baseline: 9.5813x; 1.1712x over previous
#include <cuda_runtime.h>
#include <cuda_fp16.h>
#include <math_constants.h>
#include <cstdint>

// Problem constants
#define BB 8
#define TT 8192
#define DD 512
#define QQ 1024
#define CC 4096
#define MM (BB * TT)   // 65536

typedef __half h16;

// ---------------------------------------------------------------------------
// Scratch (__device__ globals; allocation-free rule)
// ---------------------------------------------------------------------------
__device__ __align__(16) h16 g_x_hi[(size_t)MM * DD];
__device__ __align__(16) h16 g_x_lo[(size_t)MM * DD];
__device__ __align__(16) h16 g_w2t_hi[(size_t)CC * DD];   // W2^T [C][D]
__device__ __align__(16) h16 g_w2t_lo[(size_t)CC * DD];
__device__ __align__(16) h16 g_ew_hi[(size_t)QQ * DD];
__device__ __align__(16) h16 g_sc[(size_t)MM * CC];       // approx scores (512 MB)
__device__ float g_csq[CC];
__device__ unsigned long long g_key[MM];

// ---------------------------------------------------------------------------
// PTX helpers
// ---------------------------------------------------------------------------
__device__ __forceinline__ uint32_t smem_u32(const void* p) {
    uint32_t a;
    asm("{ .reg .u64 t; cvta.to.shared.u64 t, %1; cvt.u32.u64 %0, t; }"
        : "=r"(a) : "l"(p));
    return a;
}
__device__ __forceinline__ void cp16(uint32_t dst, const void* src) {
    asm volatile("cp.async.cg.shared.global [%0], [%1], 16;" :: "r"(dst), "l"(src));
}
#define CP_COMMIT() asm volatile("cp.async.commit_group;")
#define CP_WAIT1()  asm volatile("cp.async.wait_group 1;")
#define CP_WAIT0()  asm volatile("cp.async.wait_group 0;")

__device__ __forceinline__ void ldmx4(uint32_t* r, uint32_t addr) {
    asm volatile("ldmatrix.sync.aligned.m8n8.x4.shared.b16 {%0,%1,%2,%3}, [%4];"
                 : "=r"(r[0]), "=r"(r[1]), "=r"(r[2]), "=r"(r[3]) : "r"(addr));
}
__device__ __forceinline__ void mma16816_f32(float* d, const uint32_t* a,
                                             uint32_t b0, uint32_t b1) {
    asm volatile("mma.sync.aligned.m16n8k16.row.col.f32.f16.f16.f32 "
                 "{%0,%1,%2,%3}, {%4,%5,%6,%7}, {%8,%9}, {%0,%1,%2,%3};"
                 : "+f"(d[0]), "+f"(d[1]), "+f"(d[2]), "+f"(d[3])
                 : "r"(a[0]), "r"(a[1]), "r"(a[2]), "r"(a[3]), "r"(b0), "r"(b1));
}
__device__ __forceinline__ void mma16816_f16(uint32_t* d, const uint32_t* a,
                                             uint32_t b0, uint32_t b1) {
    asm volatile("mma.sync.aligned.m16n8k16.row.col.f16.f16.f16.f16 "
                 "{%0,%1}, {%2,%3,%4,%5}, {%6,%7}, {%0,%1};"
                 : "+r"(d[0]), "+r"(d[1])
                 : "r"(a[0]), "r"(a[1]), "r"(a[2]), "r"(a[3]), "r"(b0), "r"(b1));
}

// float <-> order-preserving uint32 (ascending)
__device__ __forceinline__ uint32_t ford(float s) {
    uint32_t b = __float_as_uint(s);
    return (b & 0x80000000u) ? ~b : (b | 0x80000000u);
}
__device__ __forceinline__ float unford(uint32_t f) {
    uint32_t b = (f & 0x80000000u) ? (f & 0x7FFFFFFFu) : ~f;
    return __uint_as_float(b);
}

// ---------------------------------------------------------------------------
// Shared GEMM skeleton constants: BM=BN=128, BK=64, 256 thr, 3-stage cp.async
// ---------------------------------------------------------------------------
#define T_A    0
#define T_B    16384
#define STG1   32768
#define NSTAGE 3
#define SMEM_TOTAL (NSTAGE * STG1)

#define GEMM_PRE()                                                            \
    extern __shared__ __align__(1024) char smem[];                            \
    const uint32_t sb = smem_u32(smem);                                       \
    const int tid  = threadIdx.x;                                             \
    const int lane = tid & 31;                                                \
    const int wid  = tid >> 5;                                                \
    const int wy   = wid >> 2;                                                \
    const int wx   = wid & 3;                                                 \
    const size_t bm = (size_t)blockIdx.y * 128;                               \
    const size_t bn = (size_t)blockIdx.x * 128;                               \
    const int lrow  = tid >> 1;                                               \
    const int lhalf = tid & 1;                                                \
    const uint32_t swr   = (uint32_t)((lrow & 7) << 4);                       \
    const uint32_t rbase = (uint32_t)(lrow * 128);                            \
    const char* pA = (const char*)(A + (bm + lrow) * (size_t)K);              \
    const char* pB = (const char*)(B + (bn + lrow) * (size_t)K);              \
    const int nch = K >> 6;                                                   \
    auto load_stage = [&](int s, int kc) {                                    \
        uint32_t st = sb + (uint32_t)s * STG1;                                \
        int kbyte0 = kc << 7;                                                 \
        _Pragma("unroll")                                                     \
        for (int i = 0; i < 4; i++) {                                         \
            uint32_t ko = (uint32_t)(lhalf * 64 + i * 16);                    \
            uint32_t d  = rbase + (ko ^ swr);                                 \
            cp16(st + T_A + d, pA + kbyte0 + ko);                             \
            cp16(st + T_B + d, pB + kbyte0 + ko);                             \
        }                                                                     \
        CP_COMMIT();                                                          \
    };                                                                        \
    const int rl  = lane & 15;                                                \
    const uint32_t kbh = (uint32_t)((lane >> 4) << 4);                        \
    uint32_t a_base[4], a_swz[4], b_base[2], b_swz[2];                        \
    _Pragma("unroll")                                                         \
    for (int mf = 0; mf < 4; mf++) {                                          \
        int r = wy * 64 + mf * 16 + rl;                                       \
        a_base[mf] = (uint32_t)(r * 128);                                     \
        a_swz[mf]  = (uint32_t)((r & 7) << 4);                                \
    }                                                                         \
    _Pragma("unroll")                                                         \
    for (int np = 0; np < 2; np++) {                                          \
        int n = wx * 32 + np * 16 + rl;                                       \
        b_base[np] = (uint32_t)(n * 128);                                     \
        b_swz[np]  = (uint32_t)((n & 7) << 4);                                \
    }

#define GEMM_MAINLOOP()                                                       \
    load_stage(0, 0);                                                         \
    if (nch > 1) load_stage(1, 1);                                            \
    int sidx = 0;                                                             \
    for (int kc = 0; kc < nch; kc++) {                                        \
        if (kc + 1 < nch) { CP_WAIT1(); } else { CP_WAIT0(); }                \
        __syncthreads();                                                      \
        if (kc + 2 < nch) {                                                   \
            int s2 = sidx + 2; if (s2 >= NSTAGE) s2 -= NSTAGE;                \
            load_stage(s2, kc + 2);                                           \
        }                                                                     \
        compute_stage(sidx);                                                  \
        if (++sidx == NSTAGE) sidx = 0;                                       \
    }

// ---------------------------------------------------------------------------
// Encoder GEMM: fp32 accum, 1-pass hi. outf = A@B^T + bias.
// ---------------------------------------------------------------------------
__global__ __launch_bounds__(256, 2) void hgemm_enc(
    const h16* __restrict__ A, const h16* __restrict__ B,
    int K, int Ntot, const float* __restrict__ bias, float* __restrict__ outf)
{
    GEMM_PRE();

    float acc[4][4][4];
    #pragma unroll
    for (int i = 0; i < 4; i++)
        #pragma unroll
        for (int j = 0; j < 4; j++)
            #pragma unroll
            for (int k = 0; k < 4; k++) acc[i][j][k] = 0.f;

    auto compute_stage = [&](int s) {
        uint32_t base = sb + (uint32_t)s * STG1;
        uint32_t aP = base + T_A, bP = base + T_B;
        #pragma unroll
        for (int ks = 0; ks < 4; ks++) {
            uint32_t kb = (uint32_t)(ks * 32) + kbh;
            uint32_t a_h[4][4], b_h[2][4];
            #pragma unroll
            for (int mf = 0; mf < 4; mf++)
                ldmx4(a_h[mf], aP + a_base[mf] + (kb ^ a_swz[mf]));
            #pragma unroll
            for (int np = 0; np < 2; np++)
                ldmx4(b_h[np], bP + b_base[np] + (kb ^ b_swz[np]));
            #pragma unroll
            for (int mf = 0; mf < 4; mf++)
                #pragma unroll
                for (int nf = 0; nf < 4; nf++) {
                    int p = nf >> 1, q = nf & 1;
                    mma16816_f32(acc[mf][nf], a_h[mf], b_h[p][q], b_h[p][q + 2]);
                }
        }
    };

    GEMM_MAINLOOP();

    const int qrow = lane >> 2;
    const int c2   = 2 * (lane & 3);
    #pragma unroll
    for (int mf = 0; mf < 4; mf++) {
        size_t r0 = bm + (size_t)(wy * 64 + mf * 16 + qrow);
        #pragma unroll
        for (int nf = 0; nf < 4; nf++) {
            size_t col = bn + (size_t)(wx * 32 + nf * 8 + c2);
            float b0 = bias[col], b1 = bias[col + 1];
            #pragma unroll
            for (int sub = 0; sub < 2; sub++) {
                size_t r = r0 + sub * 8;
                float2 o;
                o.x = acc[mf][nf][sub * 2 + 0] + b0;
                o.y = acc[mf][nf][sub * 2 + 1] + b1;
                *(float2*)(outf + r * Ntot + col) = o;
            }
        }
    }
}

// ---------------------------------------------------------------------------
// Screen GEMM: f16 accum (2x HMMA rate hypothesis), 1-pass hi.
// score = csq[c] - 2*dot; store fp16 score + per-row packed atomicMin.
// ---------------------------------------------------------------------------
__global__ __launch_bounds__(256, 2) void hgemm_screen(
    const h16* __restrict__ A, const h16* __restrict__ B, int K)
{
    GEMM_PRE();

    uint32_t acc[4][4][2];   // half2 pairs: [sub] -> rows r, r+8; cols c,c+1
    #pragma unroll
    for (int i = 0; i < 4; i++)
        #pragma unroll
        for (int j = 0; j < 4; j++) { acc[i][j][0] = 0u; acc[i][j][1] = 0u; }

    auto compute_stage = [&](int s) {
        uint32_t base = sb + (uint32_t)s * STG1;
        uint32_t aP = base + T_A, bP = base + T_B;
        #pragma unroll
        for (int ks = 0; ks < 4; ks++) {
            uint32_t kb = (uint32_t)(ks * 32) + kbh;
            uint32_t a_h[4][4], b_h[2][4];
            #pragma unroll
            for (int mf = 0; mf < 4; mf++)
                ldmx4(a_h[mf], aP + a_base[mf] + (kb ^ a_swz[mf]));
            #pragma unroll
            for (int np = 0; np < 2; np++)
                ldmx4(b_h[np], bP + b_base[np] + (kb ^ b_swz[np]));
            #pragma unroll
            for (int mf = 0; mf < 4; mf++)
                #pragma unroll
                for (int nf = 0; nf < 4; nf++) {
                    int p = nf >> 1, q = nf & 1;
                    mma16816_f16(acc[mf][nf], a_h[mf], b_h[p][q], b_h[p][q + 2]);
                }
        }
    };

    GEMM_MAINLOOP();

    const int qrow = lane >> 2;
    const int c2   = 2 * (lane & 3);
    #pragma unroll
    for (int mf = 0; mf < 4; mf++) {
        #pragma unroll
        for (int sub = 0; sub < 2; sub++) {
            size_t row = bm + (size_t)(wy * 64 + mf * 16 + sub * 8 + qrow);
            unsigned long long best = 0xFFFFFFFFFFFFFFFFull;
            #pragma unroll
            for (int nf = 0; nf < 4; nf++) {
                int col = (int)bn + wx * 32 + nf * 8 + c2;
                __half2 d2 = *(__half2*)&acc[mf][nf][sub];
                float s0 = g_csq[col]     - 2.0f * __half2float(__low2half(d2));
                float s1 = g_csq[col + 1] - 2.0f * __half2float(__high2half(d2));
                __half2 hp = __floats2half2_rn(s0, s1);
                uint32_t u; *(__half2*)&u = hp;
                __stcs((uint32_t*)(g_sc + row * CC + col), u);
                unsigned long long k0 =
                    ((unsigned long long)ford(s0) << 32) | (uint32_t)col;
                unsigned long long k1 =
                    ((unsigned long long)ford(s1) << 32) | (uint32_t)(col + 1);
                if (k0 < best) best = k0;
                if (k1 < best) best = k1;
            }
            unsigned long long o;
            o = __shfl_down_sync(0xFFFFFFFFu, best, 2);
            if (o < best) best = o;
            o = __shfl_down_sync(0xFFFFFFFFu, best, 1);
            if (o < best) best = o;
            if ((lane & 3) == 0) atomicMin(&g_key[row], best);
        }
    }
}

// ---------------------------------------------------------------------------
// Refine: candidates = { c : sc16[c] <= approx_min + MARGIN }; exact fp32
// recompute (hi+lo), argmin with low-index tie break. One warp per row.
// MARGIN covers dropped-lo (~0.6), f16-accum rounding (~1.0, 6sig),
// fp16 store ulp (0.5) -> 2*delta ~ 4.2; use 8.
// ---------------------------------------------------------------------------
#define MARGIN 8.0f

__global__ __launch_bounds__(256) void refine_kernel(float* __restrict__ labels) {
    int warp = blockIdx.x * 8 + (threadIdx.x >> 5);
    int lane = threadIdx.x & 31;
    size_t row = (size_t)warp;

    float amin   = unford((uint32_t)(g_key[row] >> 32));
    float thresh = amin + MARGIN;
    __half hthr  = __float2half_ru(thresh);

    const h16* sr = g_sc + row * CC;
    float best = CUDART_INF_F;
    int bestc = 0;

    for (int base = 0; base < CC; base += 256) {
        // each lane: 8 scores via uint4
        uint4 v = *(const uint4*)(sr + base + lane * 8);
        __half2 p[4];
        p[0] = *(__half2*)&v.x; p[1] = *(__half2*)&v.y;
        p[2] = *(__half2*)&v.z; p[3] = *(__half2*)&v.w;
        __half2 mn2 = __hmin2(__hmin2(p[0], p[1]), __hmin2(p[2], p[3]));
        __half mn = __hmin(__low2half(mn2), __high2half(mn2));
        uint32_t mask = __ballot_sync(0xFFFFFFFFu, __hle(mn, hthr));
        while (mask) {
            int bit = __ffs(mask) - 1;
            mask &= mask - 1;
            // lane 'bit' has >=1 candidate among its 8 scores
            #pragma unroll
            for (int j = 0; j < 8; j++) {
                float sv = __half2float(__shfl_sync(0xFFFFFFFFu,
                             ((const __half*)p)[j], bit));
                if (sv > thresh) continue;
                int c = base + bit * 8 + j;
                const h16* xh = g_x_hi + row * DD;
                const h16* xl = g_x_lo + row * DD;
                const h16* wh = g_w2t_hi + (size_t)c * DD;
                const h16* wl = g_w2t_lo + (size_t)c * DD;
                float dot = 0.f;
                #pragma unroll
                for (int jj = 0; jj < 16; jj++) {
                    int d = lane + 32 * jj;
                    float a = __half2float(xh[d]) + __half2float(xl[d]);
                    float b = __half2float(wh[d]) + __half2float(wl[d]);
                    dot = fmaf(a, b, dot);
                }
                #pragma unroll
                for (int off = 16; off > 0; off >>= 1)
                    dot += __shfl_down_sync(0xFFFFFFFFu, dot, off);
                if (lane == 0) {
                    float sc = g_csq[c] - 2.0f * dot;
                    if (sc < best || (sc == best && c < bestc)) { best = sc; bestc = c; }
                }
            }
        }
    }
    if (lane == 0) labels[row] = (float)bestc;
}

// ---------------------------------------------------------------------------
// W2^T precompute: W2T[c][d] = sum_q cb[q][c]*projw[q][d], fp32, split fp16.
// ---------------------------------------------------------------------------
__global__ __launch_bounds__(256) void w2t_kernel(const float* __restrict__ projw,
                                                  const float* __restrict__ cb) {
    __shared__ __align__(16) float As[8][128];
    __shared__ __align__(16) float Bs[8][128];

    int tid = threadIdx.x;
    int c0 = blockIdx.x * 128;
    int d0 = blockIdx.y * 128;
    int lr = tid >> 5, lc = (tid & 31) * 4;
    int ty = tid >> 4, tx = tid & 15;

    float acc[8][8];
    #pragma unroll
    for (int i = 0; i < 8; i++)
        #pragma unroll
        for (int j = 0; j < 8; j++) acc[i][j] = 0.f;

    for (int k0 = 0; k0 < QQ; k0 += 8) {
        *(float4*)&As[lr][lc] = *(const float4*)(cb + (size_t)(k0 + lr) * CC + c0 + lc);
        *(float4*)&Bs[lr][lc] = *(const float4*)(projw + (size_t)(k0 + lr) * DD + d0 + lc);
        __syncthreads();
        #pragma unroll
        for (int k = 0; k < 8; k++) {
            float ar[8], br[8];
            float4 a0 = *(const float4*)&As[k][ty * 8];
            float4 a1 = *(const float4*)&As[k][ty * 8 + 4];
            float4 b0 = *(const float4*)&Bs[k][tx * 8];
            float4 b1 = *(const float4*)&Bs[k][tx * 8 + 4];
            ar[0]=a0.x; ar[1]=a0.y; ar[2]=a0.z; ar[3]=a0.w;
            ar[4]=a1.x; ar[5]=a1.y; ar[6]=a1.z; ar[7]=a1.w;
            br[0]=b0.x; br[1]=b0.y; br[2]=b0.z; br[3]=b0.w;
            br[4]=b1.x; br[5]=b1.y; br[6]=b1.z; br[7]=b1.w;
            #pragma unroll
            for (int i = 0; i < 8; i++)
                #pragma unroll
                for (int j = 0; j < 8; j++)
                    acc[i][j] = fmaf(ar[i], br[j], acc[i][j]);
        }
        __syncthreads();
    }

    #pragma unroll
    for (int i = 0; i < 8; i++) {
        size_t rowo = (size_t)(c0 + ty * 8 + i) * DD + d0 + tx * 8;
        #pragma unroll
        for (int j = 0; j < 8; j++) {
            float v = acc[i][j];
            h16 h = __float2half(v);
            g_w2t_hi[rowo + j] = h;
            g_w2t_lo[rowo + j] = __float2half(v - __half2float(h));
        }
    }
}

// ---------------------------------------------------------------------------
// LayerNorm over D=512, writes fp16 hi/lo split.
// ---------------------------------------------------------------------------
__global__ __launch_bounds__(256) void ln_kernel(const float* __restrict__ x,
                                                 const float* __restrict__ gamma,
                                                 const float* __restrict__ beta) {
    int r = blockIdx.x;
    const float* xr = x + (size_t)r * DD;
    int t = threadIdx.x;

    float v0 = xr[t], v1 = xr[t + 256];
    float s = v0 + v1, ss = v0 * v0 + v1 * v1;
    #pragma unroll
    for (int off = 16; off > 0; off >>= 1) {
        s  += __shfl_down_sync(0xFFFFFFFFu, s,  off);
        ss += __shfl_down_sync(0xFFFFFFFFu, ss, off);
    }
    __shared__ float sh_s[8], sh_ss[8];
    int w = t >> 5, l = t & 31;
    if (l == 0) { sh_s[w] = s; sh_ss[w] = ss; }
    __syncthreads();
    if (t == 0) {
        float S = 0.f, SS = 0.f;
        #pragma unroll
        for (int i = 0; i < 8; i++) { S += sh_s[i]; SS += sh_ss[i]; }
        sh_s[0]  = S * (1.0f / DD);
        sh_ss[0] = SS * (1.0f / DD);
    }
    __syncthreads();
    float mu = sh_s[0];
    float rs = rsqrtf(sh_ss[0] - mu * mu + 1e-5f);

    float y0 = (v0 - mu) * rs * gamma[t]       + beta[t];
    float y1 = (v1 - mu) * rs * gamma[t + 256] + beta[t + 256];

    size_t base = (size_t)r * DD;
    h16 h0 = __float2half(y0), h1 = __float2half(y1);
    g_x_hi[base + t]       = h0;
    g_x_hi[base + t + 256] = h1;
    g_x_lo[base + t]       = __float2half(y0 - __half2float(h0));
    g_x_lo[base + t + 256] = __float2half(y1 - __half2float(h1));
}

// ---------------------------------------------------------------------------
__global__ __launch_bounds__(256) void split_hi_kernel(const float* __restrict__ src,
                                                       h16* __restrict__ hi, int n) {
    int i = blockIdx.x * 256 + threadIdx.x;
    if (i < n) hi[i] = __float2half(src[i]);
}

// csq: grid (CC/256, 16); partial sums over q, atomicAdd.
__global__ __launch_bounds__(256) void csq_kernel(const float* __restrict__ cb) {
    int c  = blockIdx.x * 256 + threadIdx.x;
    int q0 = blockIdx.y * (QQ / 16);
    float s = 0.f;
    #pragma unroll 4
    for (int q = q0; q < q0 + QQ / 16; q++) {
        float v = cb[(size_t)q * CC + c];
        s += v * v;
    }
    atomicAdd(&g_csq[c], s);
}

__global__ __launch_bounds__(256) void init_kernel() {
    int i = blockIdx.x * 256 + threadIdx.x;
    g_key[i] = 0xFFFFFFFFFFFFFFFFull;
    if (i < CC) g_csq[i] = 0.f;
}

// ---------------------------------------------------------------------------
extern "C" void kernel_launch(void* const* d_in, const int* in_sizes, int n_in,
                              void* d_out, int out_size) {
    const float* x     = (const float*)d_in[0];
    const float* gamma = (const float*)d_in[1];
    const float* beta  = (const float*)d_in[2];
    const float* projw = (const float*)d_in[3];
    const float* cb    = (const float*)d_in[4];
    const float* encw  = (const float*)d_in[5];
    const float* encb  = (const float*)d_in[6];

    float* out     = (float*)d_out;
    float* enc_out = out;                               // (M, Q) fp32
    float* labels  = out + ((size_t)out_size - MM);     // (M,) as fp32

    h16 *xh, *w2h, *ewh;
    cudaGetSymbolAddress((void**)&xh, g_x_hi);
    cudaGetSymbolAddress((void**)&w2h, g_w2t_hi);
    cudaGetSymbolAddress((void**)&ewh, g_ew_hi);

    cudaFuncSetAttribute(hgemm_enc, cudaFuncAttributeMaxDynamicSharedMemorySize,
                         SMEM_TOTAL);
    cudaFuncSetAttribute(hgemm_screen, cudaFuncAttributeMaxDynamicSharedMemorySize,
                         SMEM_TOTAL);

    // 1) LayerNorm -> fp16 split
    ln_kernel<<<MM, 256>>>(x, gamma, beta);

    // 2) preprocessing
    split_hi_kernel<<<(QQ * DD + 255) / 256, 256>>>(encw, ewh, QQ * DD);
    w2t_kernel<<<dim3(CC / 128, DD / 128), 256>>>(projw, cb);
    init_kernel<<<MM / 256, 256>>>();
    csq_kernel<<<dim3(CC / 256, 16), 256>>>(cb);

    // 3) encoder_out = xnorm @ enc_w^T + enc_b (fp32-accum 1-pass)
    dim3 grid12(QQ / 128, MM / 128);
    hgemm_enc<<<grid12, 256, SMEM_TOTAL>>>(xh, ewh, DD, QQ, encb, enc_out);

    // 4) label screen (f16-accum 1-pass): scores + per-row approx min
    dim3 gridx(CC / 128, MM / 128);
    hgemm_screen<<<gridx, 256, SMEM_TOTAL>>>(xh, w2h, DD);

    // 5) exact refinement -> labels
    refine_kernel<<<MM / 8, 256>>>(labels);

    (void)in_sizes; (void)n_in;
}